// round 3
// baseline (speedup 1.0000x reference)
#include <cuda_runtime.h>

#define NN 50000
#define EE 800000

typedef unsigned long long ull;

__device__ __forceinline__ void ffma2(ull &d, ull a, ull b) {
    asm("fma.rn.f32x2 %0, %1, %2, %0;" : "+l"(d) : "l"(a), "l"(b));
}
__device__ __forceinline__ float f2sum(ull u) {
    float lo = __uint_as_float((unsigned)u);
    float hi = __uint_as_float((unsigned)(u >> 32));
    return lo + hi;
}

// ---------------- scratch ----------------
__device__ float g_dinv[NN];
__device__ int   g_indeg[NN];
__device__ int   g_cur[NN];
__device__ int   g_off[NN + 1];
__device__ int   g_adj[EE];
__device__ int   g_bsum[64];

__device__ float g_y0[NN * 64];
__device__ float g_ax[NN * 64];
__device__ float g_raw1[NN * 128];
__device__ float g_y1[NN * 128];
__device__ float g_agg1[NN * 128];
__device__ float g_raw2[NN * 256];
__device__ float g_y3[NN * 64];

__device__ float g_ssum[512];
__device__ float g_ssq[512];
__device__ float g_bna[512];
__device__ float g_bnb[512];

// ---------------- setup ----------------
__global__ void k_zero() {
    int i = blockIdx.x * blockDim.x + threadIdx.x;
    if (i < NN) { g_indeg[i] = 0; g_cur[i] = 0; }
    if (i < 512) { g_ssum[i] = 0.f; g_ssq[i] = 0.f; }
}

__global__ void k_indeg(const int* __restrict__ dst) {
    int e = blockIdx.x * blockDim.x + threadIdx.x;
    if (e < EE) atomicAdd(&g_indeg[dst[e]], 1);
}

__global__ void k_dinv_y0(const float* __restrict__ x) {
    int idx = blockIdx.x * blockDim.x + threadIdx.x;
    if (idx < NN * 16) {
        int row = idx >> 4;
        float d = rsqrtf((float)(g_indeg[row] + 1));
        if ((idx & 15) == 0) g_dinv[row] = d;
        float4 v = ((const float4*)x)[idx];
        v.x *= d; v.y *= d; v.z *= d; v.w *= d;
        ((float4*)g_y0)[idx] = v;
    }
}

// ---------------- CSR build ----------------
__global__ void k_scan1() {
    int i = blockIdx.x * 1024 + threadIdx.x;
    int v = (i < NN) ? g_indeg[i] : 0;
    int lane = threadIdx.x & 31, wid = threadIdx.x >> 5;
    int s = v;
    #pragma unroll
    for (int o = 1; o < 32; o <<= 1) {
        int t = __shfl_up_sync(~0u, s, o);
        if (lane >= o) s += t;
    }
    __shared__ int wsum[32];
    if (lane == 31) wsum[wid] = s;
    __syncthreads();
    if (wid == 0) {
        int ws = wsum[lane];
        #pragma unroll
        for (int o = 1; o < 32; o <<= 1) {
            int t = __shfl_up_sync(~0u, ws, o);
            if (lane >= o) ws += t;
        }
        wsum[lane] = ws;
    }
    __syncthreads();
    int incl = s + (wid > 0 ? wsum[wid - 1] : 0);
    if (i < NN) g_off[i + 1] = incl;
    if (threadIdx.x == 1023) g_bsum[blockIdx.x] = incl;
}

__global__ void k_scan2() {
    if (threadIdx.x == 0) {
        int acc = 0;
        for (int b = 0; b < 49; b++) { int t = g_bsum[b]; g_bsum[b] = acc; acc += t; }
    }
}

__global__ void k_scan3() {
    int i = blockIdx.x * 1024 + threadIdx.x;
    if (i < NN) g_off[i + 1] += g_bsum[blockIdx.x];
    if (i == 0) g_off[0] = 0;
}

__global__ void k_scatter(const int* __restrict__ src, const int* __restrict__ dst) {
    int e = blockIdx.x * blockDim.x + threadIdx.x;
    if (e < EE) {
        int d = dst[e];
        int p = g_off[d] + atomicAdd(&g_cur[d], 1);
        g_adj[p] = src[e];
    }
}

// ---------------- aggregation: one warp per node ----------------
template <int W, int MODE>
__global__ void k_agg(const float* __restrict__ y, float* __restrict__ out,
                      const float* __restrict__ bm3, const float* __restrict__ bl3,
                      float* __restrict__ out_ls) {
    int gw = (blockIdx.x * blockDim.x + threadIdx.x) >> 5;
    if (gw >= NN) return;
    int lane = threadIdx.x & 31;
    int beg = g_off[gw], end = g_off[gw + 1];
    if (W == 64) {
        float2 acc = *(const float2*)(y + gw * 64 + lane * 2);
        for (int j = beg; j < end; j++) {
            int s = g_adj[j];
            float2 v = __ldg((const float2*)(y + s * 64 + lane * 2));
            acc.x += v.x; acc.y += v.y;
        }
        float d = g_dinv[gw];
        acc.x *= d; acc.y *= d;
        if (MODE == 0) {
            *(float2*)(out + gw * 64 + lane * 2) = acc;
        } else {
            int c = lane * 2;
            if (c < 32) {
                out[gw * 32 + c]     = acc.x + bm3[c];
                out[gw * 32 + c + 1] = acc.y + bm3[c + 1];
            } else {
                out_ls[gw * 32 + c - 32] = fminf(acc.x + bl3[c - 32], 10.0f);
                out_ls[gw * 32 + c - 31] = fminf(acc.y + bl3[c - 31], 10.0f);
            }
        }
    } else {
        float4 acc = *(const float4*)(y + gw * 128 + lane * 4);
        for (int j = beg; j < end; j++) {
            int s = g_adj[j];
            float4 v = __ldg((const float4*)(y + s * 128 + lane * 4));
            acc.x += v.x; acc.y += v.y; acc.z += v.z; acc.w += v.w;
        }
        float d = g_dinv[gw];
        acc.x *= d; acc.y *= d; acc.z *= d; acc.w *= d;
        *(float4*)(out + gw * 128 + lane * 4) = acc;
    }
}

// ---------------- layer-1 GEMM (f32x2 k-pair packed) ----------------
// raw1[:,0:64]=ax@Wm1+bm1, [:,64:128]=ax@Wl1+bl1 + BN stats (cols>=64 relu first)
// dyn smem: Wt 128*66 + As 64*64
__global__ void __launch_bounds__(256) k_gemm1(
        const float* __restrict__ A, const float* __restrict__ W1,
        const float* __restrict__ W2, const float* __restrict__ b1,
        const float* __restrict__ b2, float* __restrict__ C) {
    extern __shared__ float sm1[];
    float* Wt = sm1;             // [c][k] stride 66, c=0..127
    float* As = sm1 + 128 * 66;  // [r][64]
    int tid = threadIdx.x;
    int row0 = blockIdx.x * 64;

    // transposed W fill: 2 * 4096 elems
    for (int i = tid; i < 8192; i += 256) {
        int half = i >> 12, j = i & 4095;
        int k = j >> 6, c = j & 63;
        float v = half ? W2[k * 64 + c] : W1[k * 64 + c];
        Wt[(c + 64 * half) * 66 + k] = v;
    }
    for (int i = tid; i < 1024; i += 256) {
        int r = i >> 4, q = i & 15;
        float4 v = make_float4(0.f, 0.f, 0.f, 0.f);
        if (row0 + r < NN) v = ((const float4*)(A + (row0 + r) * 64))[q];
        ((float4*)(As + r * 64))[q] = v;
    }
    __syncthreads();

    int tx = tid & 31, ty = tid >> 5;
    ull acc[8][4];
    #pragma unroll
    for (int i = 0; i < 8; i++)
        #pragma unroll
        for (int j = 0; j < 4; j++) acc[i][j] = 0ull;

    #pragma unroll 4
    for (int kp = 0; kp < 32; kp++) {
        int k2 = kp * 2;
        ull w2[4], a2[8];
        #pragma unroll
        for (int j = 0; j < 4; j++)
            w2[j] = *(const ull*)(Wt + (tx + 32 * j) * 66 + k2);
        #pragma unroll
        for (int i = 0; i < 8; i++)
            a2[i] = *(const ull*)(As + (ty * 8 + i) * 64 + k2);
        #pragma unroll
        for (int i = 0; i < 8; i++)
            #pragma unroll
            for (int j = 0; j < 4; j++)
                ffma2(acc[i][j], a2[i], w2[j]);
    }

    float bb[4];
    bb[0] = b1[tx]; bb[1] = b1[tx + 32]; bb[2] = b2[tx]; bb[3] = b2[tx + 32];

    float ls[4] = {0.f, 0.f, 0.f, 0.f}, l2[4] = {0.f, 0.f, 0.f, 0.f};
    #pragma unroll
    for (int i = 0; i < 8; i++) {
        int r = row0 + ty * 8 + i;
        if (r < NN) {
            #pragma unroll
            for (int j = 0; j < 4; j++) {
                float v = f2sum(acc[i][j]) + bb[j];
                C[(size_t)r * 128 + tx + 32 * j] = v;
                float sv = (j < 2) ? v : fmaxf(v, 0.f);
                ls[j] += sv; l2[j] += sv * sv;
            }
        }
    }
    __syncthreads();
    float* red = As;
    red[tid] = 0.f;
    __syncthreads();
    #pragma unroll
    for (int j = 0; j < 4; j++) {
        atomicAdd(&red[tx + 32 * j], ls[j]);
        atomicAdd(&red[128 + tx + 32 * j], l2[j]);
    }
    __syncthreads();
    if (tid < 128) {
        atomicAdd(&g_ssum[tid], red[tid]);
        atomicAdd(&g_ssq[tid], red[tid + 128]);
    }
}

__global__ void k_statfin(int base, int C, const float* __restrict__ g1,
                          const float* __restrict__ h1, const float* __restrict__ g2,
                          const float* __restrict__ h2, int half) {
    int c = threadIdx.x;
    if (c < C) {
        float m = g_ssum[base + c] * (1.0f / NN);
        float v = g_ssq[base + c] * (1.0f / NN) - m * m;
        float rstd = rsqrtf(v + 1e-5f);
        float gamma = (c < half) ? g1[c] : g2[c - half];
        float beta  = (c < half) ? h1[c] : h2[c - half];
        float a = gamma * rstd;
        g_bna[base + c] = a;
        g_bnb[base + c] = beta - m * a;
    }
}

__global__ void k_ew1() {
    int idx = blockIdx.x * blockDim.x + threadIdx.x;
    if (idx >= NN * 32) return;
    int r = idx >> 5;
    int c4 = (idx & 31) << 2;
    float4 v = ((const float4*)g_raw1)[idx];
    float d = g_dinv[r];
    float o[4]; float vv[4] = {v.x, v.y, v.z, v.w};
    #pragma unroll
    for (int t = 0; t < 4; t++) {
        int c = c4 + t;
        float a = g_bna[c], b = g_bnb[c];
        if (c4 < 64) o[t] = fmaxf(vv[t] * a + b, 0.f);
        else         o[t] = fmaxf(vv[t], 0.f) * a + b;
        o[t] *= d;
    }
    ((float4*)g_y1)[idx] = make_float4(o[0], o[1], o[2], o[3]);
}

// ---------------- layer-2 GEMM (f32x2) ----------------
// 32 rows/block. raw2[:,0:128]=agg1[:,0:64]@Wm2+bm2; [:,128:256]=agg1[:,64:128]@Wl2+bl2
// dyn smem: Wt 256*66 + As 32*128
__global__ void __launch_bounds__(256) k_gemm2(
        const float* __restrict__ A, const float* __restrict__ W1,
        const float* __restrict__ W2, const float* __restrict__ b1,
        const float* __restrict__ b2, float* __restrict__ C) {
    extern __shared__ float sm2[];
    float* Wt = sm2;             // [c][k] stride 66, c=0..255
    float* As = sm2 + 256 * 66;  // [r][128]
    int tid = threadIdx.x;
    int row0 = blockIdx.x * 32;

    for (int i = tid; i < 16384; i += 256) {
        int half = i >> 13, j = i & 8191;
        int k = j >> 7, c = j & 127;
        float v = half ? W2[k * 128 + c] : W1[k * 128 + c];
        Wt[(c + 128 * half) * 66 + k] = v;
    }
    for (int i = tid; i < 1024; i += 256) {
        int r = i >> 5, q = i & 31;
        float4 v = make_float4(0.f, 0.f, 0.f, 0.f);
        if (row0 + r < NN) v = ((const float4*)(A + (size_t)(row0 + r) * 128))[q];
        ((float4*)(As + r * 128))[q] = v;
    }
    __syncthreads();

    int tx = tid & 31, ty = tid >> 5;   // ty: 8 groups of 4 rows
    ull acc[4][8];
    #pragma unroll
    for (int i = 0; i < 4; i++)
        #pragma unroll
        for (int j = 0; j < 8; j++) acc[i][j] = 0ull;

    #pragma unroll 4
    for (int kp = 0; kp < 32; kp++) {
        int k2 = kp * 2;
        ull w2[8], alo[4], ahi[4];
        #pragma unroll
        for (int j = 0; j < 8; j++)
            w2[j] = *(const ull*)(Wt + (tx + 32 * j) * 66 + k2);
        #pragma unroll
        for (int i = 0; i < 4; i++) {
            alo[i] = *(const ull*)(As + (ty * 4 + i) * 128 + k2);
            ahi[i] = *(const ull*)(As + (ty * 4 + i) * 128 + 64 + k2);
        }
        #pragma unroll
        for (int i = 0; i < 4; i++)
            #pragma unroll
            for (int j = 0; j < 8; j++)
                ffma2(acc[i][j], (j < 4 ? alo[i] : ahi[i]), w2[j]);
    }

    float bb[8];
    #pragma unroll
    for (int j = 0; j < 8; j++)
        bb[j] = (j < 4) ? b1[tx + 32 * j] : b2[tx + 32 * j - 128];

    float ls[8], l2[8];
    #pragma unroll
    for (int j = 0; j < 8; j++) { ls[j] = 0.f; l2[j] = 0.f; }
    #pragma unroll
    for (int i = 0; i < 4; i++) {
        int r = row0 + ty * 4 + i;
        if (r < NN) {
            #pragma unroll
            for (int j = 0; j < 8; j++) {
                float v = f2sum(acc[i][j]) + bb[j];
                C[(size_t)r * 256 + tx + 32 * j] = v;
                float sv = (j < 4) ? v : fmaxf(v, 0.f);
                ls[j] += sv; l2[j] += sv * sv;
            }
        }
    }
    __syncthreads();
    float* red = As;
    red[tid] = 0.f; red[tid + 256] = 0.f;
    __syncthreads();
    #pragma unroll
    for (int j = 0; j < 8; j++) {
        atomicAdd(&red[tx + 32 * j], ls[j]);
        atomicAdd(&red[256 + tx + 32 * j], l2[j]);
    }
    __syncthreads();
    atomicAdd(&g_ssum[256 + tid], red[tid]);
    atomicAdd(&g_ssq[256 + tid], red[tid + 256]);
}

// ---------------- layer-3 GEMM with BN-on-load (f32x2) ----------------
// dyn smem: Wt 64*130 + As 128*64
__global__ void __launch_bounds__(256) k_gemm3(
        const float* __restrict__ raw2, const float* __restrict__ Wm3,
        const float* __restrict__ Wl3, float* __restrict__ y3) {
    extern __shared__ float sm3[];
    float* Wt = sm3;             // [c][k] stride 130, c=0..63 (c<32 mu)
    float* As = sm3 + 64 * 130;  // [r][2 halves x 32 k]
    int tid = threadIdx.x;
    int row0 = blockIdx.x * 128;

    for (int i = tid; i < 8192; i += 256) {
        int half = i >> 12, j = i & 4095;
        int k = j >> 5, c = j & 31;
        float v = half ? Wl3[k * 32 + c] : Wm3[k * 32 + c];
        Wt[(c + 32 * half) * 130 + k] = v;
    }

    int tx = tid & 15, ty = tid >> 4;
    int half_c = (tx >= 8) ? 1 : 0;
    ull acc[8][4];
    #pragma unroll
    for (int i = 0; i < 8; i++)
        #pragma unroll
        for (int j = 0; j < 4; j++) acc[i][j] = 0ull;

    for (int kt = 0; kt < 128; kt += 32) {
        __syncthreads();
        for (int i = tid; i < 2048; i += 256) {
            int r = i >> 4, q = i & 15;
            int half = q >> 3, kk = (q & 7) << 2;
            float4 v = make_float4(0.f, 0.f, 0.f, 0.f);
            if (row0 + r < NN)
                v = ((const float4*)(raw2 + (size_t)(row0 + r) * 256 + half * 128 + kt))[q & 7];
            float o[4]; float vv[4] = {v.x, v.y, v.z, v.w};
            #pragma unroll
            for (int t = 0; t < 4; t++) {
                int col = 256 + half * 128 + kt + kk + t;
                float a = g_bna[col], b = g_bnb[col];
                if (half == 0) o[t] = fmaxf(vv[t] * a + b, 0.f);
                else           o[t] = fmaxf(vv[t], 0.f) * a + b;
            }
            ((float4*)(As + r * 64 + half * 32))[(kk >> 2)] =
                make_float4(o[0], o[1], o[2], o[3]);
        }
        __syncthreads();
        #pragma unroll 4
        for (int kp = 0; kp < 16; kp++) {
            int k2 = kp * 2;
            ull w2[4], a2[8];
            #pragma unroll
            for (int j = 0; j < 4; j++)
                w2[j] = *(const ull*)(Wt + (tx * 4 + j) * 130 + kt + k2);
            #pragma unroll
            for (int i = 0; i < 8; i++)
                a2[i] = *(const ull*)(As + (ty * 8 + i) * 64 + half_c * 32 + k2);
            #pragma unroll
            for (int i = 0; i < 8; i++)
                #pragma unroll
                for (int j = 0; j < 4; j++)
                    ffma2(acc[i][j], a2[i], w2[j]);
        }
    }
    #pragma unroll
    for (int i = 0; i < 8; i++) {
        int r = row0 + ty * 8 + i;
        if (r < NN) {
            float d = g_dinv[r];
            float4 o = make_float4(f2sum(acc[i][0]) * d, f2sum(acc[i][1]) * d,
                                   f2sum(acc[i][2]) * d, f2sum(acc[i][3]) * d);
            ((float4*)(y3 + (size_t)r * 64))[tx] = o;
        }
    }
}

// ---------------- decoder ----------------
__global__ void k_dec(const int* __restrict__ src, const int* __restrict__ dst,
                      const float* __restrict__ mu, float* __restrict__ probs) {
    int t = blockIdx.x * blockDim.x + threadIdx.x;
    int e = t >> 3, sub = t & 7;
    int s = src[e], d = dst[e];
    float4 a = __ldg((const float4*)(mu + s * 32 + sub * 4));
    float4 b = __ldg((const float4*)(mu + d * 32 + sub * 4));
    float p = a.x * b.x + a.y * b.y + a.z * b.z + a.w * b.w;
    p += __shfl_down_sync(~0u, p, 4);
    p += __shfl_down_sync(~0u, p, 2);
    p += __shfl_down_sync(~0u, p, 1);
    if (sub == 0) probs[e] = 1.f / (1.f + expf(-p));
}

// ---------------- launch ----------------
extern "C" void kernel_launch(void* const* d_in, const int* in_sizes, int n_in,
                              void* d_out, int out_size) {
    const float* x   = (const float*)d_in[0];
    const int* ei    = (const int*)d_in[1];
    const int* src   = ei;
    const int* dst   = ei + EE;
    const float* Wm1 = (const float*)d_in[2];
    const float* bm1 = (const float*)d_in[3];
    const float* gm1 = (const float*)d_in[4];
    const float* hm1 = (const float*)d_in[5];
    const float* Wm2 = (const float*)d_in[6];
    const float* bm2 = (const float*)d_in[7];
    const float* gm2 = (const float*)d_in[8];
    const float* hm2 = (const float*)d_in[9];
    const float* Wm3 = (const float*)d_in[10];
    const float* bm3 = (const float*)d_in[11];
    const float* Wl1 = (const float*)d_in[12];
    const float* bl1 = (const float*)d_in[13];
    const float* gl1 = (const float*)d_in[14];
    const float* hl1 = (const float*)d_in[15];
    const float* Wl2 = (const float*)d_in[16];
    const float* bl2 = (const float*)d_in[17];
    const float* gl2 = (const float*)d_in[18];
    const float* hl2 = (const float*)d_in[19];
    const float* Wl3 = (const float*)d_in[20];
    const float* bl3 = (const float*)d_in[21];

    float* out = (float*)d_out;
    float* out_probs = out;
    float* out_mu = out + EE;
    float* out_ls = out + EE + NN * 32;

    float *y0, *ax, *raw1, *y1, *agg1, *raw2, *y3;
    cudaGetSymbolAddress((void**)&y0, g_y0);
    cudaGetSymbolAddress((void**)&ax, g_ax);
    cudaGetSymbolAddress((void**)&raw1, g_raw1);
    cudaGetSymbolAddress((void**)&y1, g_y1);
    cudaGetSymbolAddress((void**)&agg1, g_agg1);
    cudaGetSymbolAddress((void**)&raw2, g_raw2);
    cudaGetSymbolAddress((void**)&y3, g_y3);

    const int SM1 = (128 * 66 + 64 * 64) * 4;
    const int SM2 = (256 * 66 + 32 * 128) * 4;
    const int SM3 = (64 * 130 + 128 * 64) * 4;
    cudaFuncSetAttribute(k_gemm1, cudaFuncAttributeMaxDynamicSharedMemorySize, SM1);
    cudaFuncSetAttribute(k_gemm2, cudaFuncAttributeMaxDynamicSharedMemorySize, SM2);
    cudaFuncSetAttribute(k_gemm3, cudaFuncAttributeMaxDynamicSharedMemorySize, SM3);

    // setup + degree + CSR
    k_zero<<<196, 256>>>();
    k_indeg<<<3125, 256>>>(dst);
    k_dinv_y0<<<3125, 256>>>(x);
    k_scan1<<<49, 1024>>>();
    k_scan2<<<1, 32>>>();
    k_scan3<<<49, 1024>>>();
    k_scatter<<<3125, 256>>>(src, dst);

    // layer 1
    k_agg<64, 0><<<6250, 256>>>(y0, ax, nullptr, nullptr, nullptr);
    k_gemm1<<<782, 256, SM1>>>(ax, Wm1, Wl1, bm1, bl1, raw1);
    k_statfin<<<1, 128>>>(0, 128, gm1, hm1, gl1, hl1, 64);
    k_ew1<<<6250, 256>>>();

    // layer 2
    k_agg<128, 0><<<6250, 256>>>(y1, agg1, nullptr, nullptr, nullptr);
    k_gemm2<<<1563, 256, SM2>>>(agg1, Wm2, Wl2, bm2, bl2, raw2);
    k_statfin<<<1, 256>>>(256, 256, gm2, hm2, gl2, hl2, 128);

    // layer 3
    k_gemm3<<<391, 256, SM3>>>(raw2, Wm3, Wl3, y3);
    k_agg<64, 1><<<6250, 256>>>(y3, out_mu, bm3, bl3, out_ls);

    // decoder
    k_dec<<<25000, 256>>>(src, dst, out_mu, out_probs);
}

// round 4
// speedup vs baseline: 1.0708x; 1.0708x over previous
#include <cuda_runtime.h>

#define NN 50000
#define EE 800000

// ---------------- scratch ----------------
__device__ float g_dinv[NN];
__device__ int   g_indeg[NN];
__device__ int   g_cur[NN];
__device__ int   g_off[NN + 1];
__device__ int   g_adj[EE];
__device__ int   g_bsum[64];

__device__ float g_ax[NN * 64];     // A_norm x
__device__ float g_raw1[NN * 128];  // [mu64 | ls64] gcn1 linear out
__device__ float g_agg1[NN * 128];  // aggregated act1
__device__ float g_raw2[NN * 256];  // [mu128 | ls128] gcn2 linear out
__device__ float g_y3[NN * 64];     // dinv * (act2 @ W3)  [mu32 | ls32]

__device__ float g_ssum[512];
__device__ float g_ssq[512];
__device__ float g_bna[512];
__device__ float g_bnb[512];

// ---------------- setup ----------------
__global__ void k_zero() {
    int i = blockIdx.x * blockDim.x + threadIdx.x;
    if (i < NN) { g_indeg[i] = 0; g_cur[i] = 0; }
    if (i < 512) { g_ssum[i] = 0.f; g_ssq[i] = 0.f; }
}

__global__ void k_indeg(const int* __restrict__ dst) {
    int e = blockIdx.x * blockDim.x + threadIdx.x;
    if (e < EE) atomicAdd(&g_indeg[dst[e]], 1);
}

__global__ void k_dinv() {
    int i = blockIdx.x * blockDim.x + threadIdx.x;
    if (i < NN) g_dinv[i] = rsqrtf((float)(g_indeg[i] + 1));
}

// ---------------- CSR build ----------------
__global__ void k_scan1() {
    int i = blockIdx.x * 1024 + threadIdx.x;
    int v = (i < NN) ? g_indeg[i] : 0;
    int lane = threadIdx.x & 31, wid = threadIdx.x >> 5;
    int s = v;
    #pragma unroll
    for (int o = 1; o < 32; o <<= 1) {
        int t = __shfl_up_sync(~0u, s, o);
        if (lane >= o) s += t;
    }
    __shared__ int wsum[32];
    if (lane == 31) wsum[wid] = s;
    __syncthreads();
    if (wid == 0) {
        int ws = wsum[lane];
        #pragma unroll
        for (int o = 1; o < 32; o <<= 1) {
            int t = __shfl_up_sync(~0u, ws, o);
            if (lane >= o) ws += t;
        }
        wsum[lane] = ws;
    }
    __syncthreads();
    int incl = s + (wid > 0 ? wsum[wid - 1] : 0);
    if (i < NN) g_off[i + 1] = incl;
    if (threadIdx.x == 1023) g_bsum[blockIdx.x] = incl;
}

__global__ void k_scan2() {
    if (threadIdx.x == 0) {
        int acc = 0;
        for (int b = 0; b < 49; b++) { int t = g_bsum[b]; g_bsum[b] = acc; acc += t; }
    }
}

__global__ void k_scan3() {
    int i = blockIdx.x * 1024 + threadIdx.x;
    if (i < NN) g_off[i + 1] += g_bsum[blockIdx.x];
    if (i == 0) g_off[0] = 0;
}

__global__ void k_scatter(const int* __restrict__ src, const int* __restrict__ dst) {
    int e = blockIdx.x * blockDim.x + threadIdx.x;
    if (e < EE) {
        int d = dst[e];
        int p = g_off[d] + atomicAdd(&g_cur[d], 1);
        g_adj[p] = src[e];
    }
}

// ---------------- layer-1 aggregation straight from x ----------------
// ax[d] = dinv[d] * ( sum_{s in N(d)} dinv[s]*x[s] + dinv[d]*x[d] )
__global__ void k_agg1x(const float* __restrict__ x, float* __restrict__ out) {
    int gw = (blockIdx.x * blockDim.x + threadIdx.x) >> 5;
    if (gw >= NN) return;
    int lane = threadIdx.x & 31;
    int beg = g_off[gw], end = g_off[gw + 1];
    float dg = g_dinv[gw];
    float2 v0 = *(const float2*)(x + gw * 64 + lane * 2);
    float2 acc = make_float2(v0.x * dg, v0.y * dg);
    for (int j = beg; j < end; j++) {
        int s = g_adj[j];
        float ds = __ldg(&g_dinv[s]);
        float2 v = __ldg((const float2*)(x + s * 64 + lane * 2));
        acc.x += v.x * ds; acc.y += v.y * ds;
    }
    acc.x *= dg; acc.y *= dg;
    *(float2*)(out + gw * 64 + lane * 2) = acc;
}

// ---------------- layer-2 aggregation from raw1, BN/ReLU on the fly ----------------
// act(v,c) = c<64 ? relu(v*a+b) : relu(v)*a+b ; y1[s] = act(raw1[s])*dinv[s]
// agg1[d] = dinv[d]*( sum y1[s] + y1[d] )
__global__ void k_agg2bn(const float* __restrict__ raw1, float* __restrict__ out) {
    int gw = (blockIdx.x * blockDim.x + threadIdx.x) >> 5;
    if (gw >= NN) return;
    int lane = threadIdx.x & 31;
    int c4 = lane * 4;
    bool bnfirst = (c4 < 64);
    float a0 = g_bna[c4], a1 = g_bna[c4 + 1], a2 = g_bna[c4 + 2], a3 = g_bna[c4 + 3];
    float b0 = g_bnb[c4], b1 = g_bnb[c4 + 1], b2 = g_bnb[c4 + 2], b3 = g_bnb[c4 + 3];

    int beg = g_off[gw], end = g_off[gw + 1];
    float dg = g_dinv[gw];

    float4 acc;
    {
        float4 v = *(const float4*)(raw1 + (size_t)gw * 128 + c4);
        float t0, t1, t2, t3;
        if (bnfirst) {
            t0 = fmaxf(v.x * a0 + b0, 0.f); t1 = fmaxf(v.y * a1 + b1, 0.f);
            t2 = fmaxf(v.z * a2 + b2, 0.f); t3 = fmaxf(v.w * a3 + b3, 0.f);
        } else {
            t0 = fmaxf(v.x, 0.f) * a0 + b0; t1 = fmaxf(v.y, 0.f) * a1 + b1;
            t2 = fmaxf(v.z, 0.f) * a2 + b2; t3 = fmaxf(v.w, 0.f) * a3 + b3;
        }
        acc = make_float4(t0 * dg, t1 * dg, t2 * dg, t3 * dg);
    }
    for (int j = beg; j < end; j++) {
        int s = g_adj[j];
        float ds = __ldg(&g_dinv[s]);
        float4 v = __ldg((const float4*)(raw1 + (size_t)s * 128 + c4));
        float t0, t1, t2, t3;
        if (bnfirst) {
            t0 = fmaxf(v.x * a0 + b0, 0.f); t1 = fmaxf(v.y * a1 + b1, 0.f);
            t2 = fmaxf(v.z * a2 + b2, 0.f); t3 = fmaxf(v.w * a3 + b3, 0.f);
        } else {
            t0 = fmaxf(v.x, 0.f) * a0 + b0; t1 = fmaxf(v.y, 0.f) * a1 + b1;
            t2 = fmaxf(v.z, 0.f) * a2 + b2; t3 = fmaxf(v.w, 0.f) * a3 + b3;
        }
        acc.x += t0 * ds; acc.y += t1 * ds; acc.z += t2 * ds; acc.w += t3 * ds;
    }
    acc.x *= dg; acc.y *= dg; acc.z *= dg; acc.w *= dg;
    *(float4*)(out + (size_t)gw * 128 + c4) = acc;
}

// ---------------- layer-3 final aggregation (bias, clamp, split) ----------------
__global__ void k_agg3f(const float* __restrict__ y, float* __restrict__ out_mu,
                        const float* __restrict__ bm3, const float* __restrict__ bl3,
                        float* __restrict__ out_ls) {
    int gw = (blockIdx.x * blockDim.x + threadIdx.x) >> 5;
    if (gw >= NN) return;
    int lane = threadIdx.x & 31;
    int beg = g_off[gw], end = g_off[gw + 1];
    float2 acc = *(const float2*)(y + gw * 64 + lane * 2);
    for (int j = beg; j < end; j++) {
        int s = g_adj[j];
        float2 v = __ldg((const float2*)(y + s * 64 + lane * 2));
        acc.x += v.x; acc.y += v.y;
    }
    float d = g_dinv[gw];
    acc.x *= d; acc.y *= d;
    int c = lane * 2;
    if (c < 32) {
        out_mu[gw * 32 + c]     = acc.x + bm3[c];
        out_mu[gw * 32 + c + 1] = acc.y + bm3[c + 1];
    } else {
        out_ls[gw * 32 + c - 32] = fminf(acc.x + bl3[c - 32], 10.0f);
        out_ls[gw * 32 + c - 31] = fminf(acc.y + bl3[c - 31], 10.0f);
    }
}

// ---------------- layer-1 fused GEMM (round-2 proven version) ----------------
__global__ void __launch_bounds__(256) k_gemm1(
        const float* __restrict__ A, const float* __restrict__ W1,
        const float* __restrict__ W2, const float* __restrict__ b1,
        const float* __restrict__ b2, float* __restrict__ C) {
    __shared__ float Ws[64 * 128];
    __shared__ float As[64 * 64];
    int tid = threadIdx.x;
    int row0 = blockIdx.x * 64;

    for (int i = tid; i < 1024; i += 256) {
        int k = i >> 4, q = i & 15;
        ((float4*)(Ws + k * 128))[q]      = ((const float4*)(W1 + k * 64))[q];
        ((float4*)(Ws + k * 128 + 64))[q] = ((const float4*)(W2 + k * 64))[q];
    }
    for (int i = tid; i < 1024; i += 256) {
        int r = i >> 4, q = i & 15;
        float4 v = make_float4(0.f, 0.f, 0.f, 0.f);
        if (row0 + r < NN) v = ((const float4*)(A + (row0 + r) * 64))[q];
        ((float4*)(As + r * 64))[q] = v;
    }
    __syncthreads();

    int tx = tid & 31, ty = tid >> 5;
    float acc[8][4];
    #pragma unroll
    for (int i = 0; i < 8; i++)
        #pragma unroll
        for (int j = 0; j < 4; j++) acc[i][j] = 0.f;

    #pragma unroll 8
    for (int k = 0; k < 64; k++) {
        float w0 = Ws[k * 128 + tx], w1 = Ws[k * 128 + tx + 32];
        float w2 = Ws[k * 128 + tx + 64], w3 = Ws[k * 128 + tx + 96];
        #pragma unroll
        for (int i = 0; i < 8; i++) {
            float a = As[(ty * 8 + i) * 64 + k];
            acc[i][0] += a * w0; acc[i][1] += a * w1;
            acc[i][2] += a * w2; acc[i][3] += a * w3;
        }
    }

    float bb[4];
    bb[0] = b1[tx]; bb[1] = b1[tx + 32]; bb[2] = b2[tx]; bb[3] = b2[tx + 32];

    float ls[4] = {0.f, 0.f, 0.f, 0.f}, l2[4] = {0.f, 0.f, 0.f, 0.f};
    #pragma unroll
    for (int i = 0; i < 8; i++) {
        int r = row0 + ty * 8 + i;
        if (r < NN) {
            #pragma unroll
            for (int j = 0; j < 4; j++) {
                float v = acc[i][j] + bb[j];
                C[(size_t)r * 128 + tx + 32 * j] = v;
                float sv = (j < 2) ? v : fmaxf(v, 0.f);
                ls[j] += sv; l2[j] += sv * sv;
            }
        }
    }
    __syncthreads();
    float* red = As;
    red[tid] = 0.f;
    __syncthreads();
    #pragma unroll
    for (int j = 0; j < 4; j++) {
        atomicAdd(&red[tx + 32 * j], ls[j]);
        atomicAdd(&red[128 + tx + 32 * j], l2[j]);
    }
    __syncthreads();
    if (tid < 128) {
        atomicAdd(&g_ssum[tid], red[tid]);
        atomicAdd(&g_ssq[tid], red[tid + 128]);
    }
}

__global__ void k_statfin(int base, int C, const float* __restrict__ g1,
                          const float* __restrict__ h1, const float* __restrict__ g2,
                          const float* __restrict__ h2, int half) {
    int c = threadIdx.x;
    if (c < C) {
        float m = g_ssum[base + c] * (1.0f / NN);
        float v = g_ssq[base + c] * (1.0f / NN) - m * m;
        float rstd = rsqrtf(v + 1e-5f);
        float gamma = (c < half) ? g1[c] : g2[c - half];
        float beta  = (c < half) ? h1[c] : h2[c - half];
        float a = gamma * rstd;
        g_bna[base + c] = a;
        g_bnb[base + c] = beta - m * a;
    }
}

// ---------------- layer-2 fused GEMM (round-2 proven version) ----------------
__global__ void __launch_bounds__(256) k_gemm2(
        const float* __restrict__ A, const float* __restrict__ W1,
        const float* __restrict__ W2, const float* __restrict__ b1,
        const float* __restrict__ b2, float* __restrict__ C) {
    extern __shared__ float sm2[];
    float* Ws = sm2;
    float* As = sm2 + 64 * 256;
    int tid = threadIdx.x;
    int row0 = blockIdx.x * 64;

    for (int i = tid; i < 2048; i += 256) {
        int k = i >> 5, q = i & 31;
        ((float4*)(Ws + k * 256))[q]       = ((const float4*)(W1 + k * 128))[q];
        ((float4*)(Ws + k * 256 + 128))[q] = ((const float4*)(W2 + k * 128))[q];
    }
    for (int i = tid; i < 2048; i += 256) {
        int r = i >> 5, q = i & 31;
        float4 v = make_float4(0.f, 0.f, 0.f, 0.f);
        if (row0 + r < NN) v = ((const float4*)(A + (size_t)(row0 + r) * 128))[q];
        ((float4*)(As + r * 128))[q] = v;
    }
    __syncthreads();

    int tx = tid & 31, ty = tid >> 5;
    float acc[8][8];
    #pragma unroll
    for (int i = 0; i < 8; i++)
        #pragma unroll
        for (int j = 0; j < 8; j++) acc[i][j] = 0.f;

    #pragma unroll 4
    for (int k = 0; k < 64; k++) {
        float w[8];
        #pragma unroll
        for (int j = 0; j < 8; j++) w[j] = Ws[k * 256 + tx + 32 * j];
        #pragma unroll
        for (int i = 0; i < 8; i++) {
            float alo = As[(ty * 8 + i) * 128 + k];
            float ahi = As[(ty * 8 + i) * 128 + 64 + k];
            #pragma unroll
            for (int j = 0; j < 8; j++)
                acc[i][j] += (j < 4 ? alo : ahi) * w[j];
        }
    }

    float bb[8];
    #pragma unroll
    for (int j = 0; j < 8; j++)
        bb[j] = (j < 4) ? b1[tx + 32 * j] : b2[tx + 32 * j - 128];

    float ls[8], l2[8];
    #pragma unroll
    for (int j = 0; j < 8; j++) { ls[j] = 0.f; l2[j] = 0.f; }
    #pragma unroll
    for (int i = 0; i < 8; i++) {
        int r = row0 + ty * 8 + i;
        if (r < NN) {
            #pragma unroll
            for (int j = 0; j < 8; j++) {
                float v = acc[i][j] + bb[j];
                C[(size_t)r * 256 + tx + 32 * j] = v;
                float sv = (j < 4) ? v : fmaxf(v, 0.f);
                ls[j] += sv; l2[j] += sv * sv;
            }
        }
    }
    __syncthreads();
    float* red = As;
    red[tid] = 0.f; red[tid + 256] = 0.f;
    __syncthreads();
    #pragma unroll
    for (int j = 0; j < 8; j++) {
        atomicAdd(&red[tx + 32 * j], ls[j]);
        atomicAdd(&red[256 + tx + 32 * j], l2[j]);
    }
    __syncthreads();
    atomicAdd(&g_ssum[256 + tid], red[tid]);
    atomicAdd(&g_ssq[256 + tid], red[tid + 256]);
}

// ---------------- layer-3 GEMM with BN-on-load (round-2 proven version) ----------------
__global__ void __launch_bounds__(256) k_gemm3(
        const float* __restrict__ raw2, const float* __restrict__ Wm3,
        const float* __restrict__ Wl3, float* __restrict__ y3) {
    extern __shared__ float sm3[];
    float* Ws = sm3;
    float* As = sm3 + 128 * 64;
    int tid = threadIdx.x;
    int row0 = blockIdx.x * 128;

    for (int i = tid; i < 2048; i += 256) {
        int k = i >> 4, q = i & 15;
        float4 v = (q < 8) ? ((const float4*)(Wm3 + k * 32))[q]
                           : ((const float4*)(Wl3 + k * 32))[q - 8];
        ((float4*)(Ws + k * 64))[q] = v;
    }

    int tx = tid & 15, ty = tid >> 4;
    int half_c = (tx >= 8) ? 1 : 0;
    float acc[8][4];
    #pragma unroll
    for (int i = 0; i < 8; i++)
        #pragma unroll
        for (int j = 0; j < 4; j++) acc[i][j] = 0.f;

    for (int kt = 0; kt < 128; kt += 32) {
        __syncthreads();
        for (int i = tid; i < 2048; i += 256) {
            int r = i >> 4, q = i & 15;
            int half = q >> 3, kk = (q & 7) << 2;
            float4 v = make_float4(0.f, 0.f, 0.f, 0.f);
            if (row0 + r < NN)
                v = ((const float4*)(raw2 + (size_t)(row0 + r) * 256 + half * 128 + kt))[q & 7];
            float o[4]; float vv[4] = {v.x, v.y, v.z, v.w};
            #pragma unroll
            for (int t = 0; t < 4; t++) {
                int col = 256 + half * 128 + kt + kk + t;
                float a = g_bna[col], b = g_bnb[col];
                if (half == 0) o[t] = fmaxf(vv[t] * a + b, 0.f);
                else           o[t] = fmaxf(vv[t], 0.f) * a + b;
            }
            ((float4*)(As + r * 64 + half * 32))[(kk >> 2)] =
                make_float4(o[0], o[1], o[2], o[3]);
        }
        __syncthreads();
        #pragma unroll 8
        for (int k = 0; k < 32; k++) {
            float4 w = ((float4*)(Ws + (kt + k) * 64))[tx];
            #pragma unroll
            for (int i = 0; i < 8; i++) {
                float a = As[(ty * 8 + i) * 64 + half_c * 32 + k];
                acc[i][0] += a * w.x; acc[i][1] += a * w.y;
                acc[i][2] += a * w.z; acc[i][3] += a * w.w;
            }
        }
    }
    #pragma unroll
    for (int i = 0; i < 8; i++) {
        int r = row0 + ty * 8 + i;
        if (r < NN) {
            float d = g_dinv[r];
            float4 o = make_float4(acc[i][0] * d, acc[i][1] * d, acc[i][2] * d, acc[i][3] * d);
            ((float4*)(y3 + (size_t)r * 64))[tx] = o;
        }
    }
}

// ---------------- decoder ----------------
__global__ void k_dec(const int* __restrict__ src, const int* __restrict__ dst,
                      const float* __restrict__ mu, float* __restrict__ probs) {
    int t = blockIdx.x * blockDim.x + threadIdx.x;
    int e = t >> 3, sub = t & 7;
    int s = src[e], d = dst[e];
    float4 a = __ldg((const float4*)(mu + s * 32 + sub * 4));
    float4 b = __ldg((const float4*)(mu + d * 32 + sub * 4));
    float p = a.x * b.x + a.y * b.y + a.z * b.z + a.w * b.w;
    p += __shfl_down_sync(~0u, p, 4);
    p += __shfl_down_sync(~0u, p, 2);
    p += __shfl_down_sync(~0u, p, 1);
    if (sub == 0) probs[e] = 1.f / (1.f + expf(-p));
}

// ---------------- launch ----------------
extern "C" void kernel_launch(void* const* d_in, const int* in_sizes, int n_in,
                              void* d_out, int out_size) {
    const float* x   = (const float*)d_in[0];
    const int* ei    = (const int*)d_in[1];
    const int* src   = ei;
    const int* dst   = ei + EE;
    const float* Wm1 = (const float*)d_in[2];
    const float* bm1 = (const float*)d_in[3];
    const float* gm1 = (const float*)d_in[4];
    const float* hm1 = (const float*)d_in[5];
    const float* Wm2 = (const float*)d_in[6];
    const float* bm2 = (const float*)d_in[7];
    const float* gm2 = (const float*)d_in[8];
    const float* hm2 = (const float*)d_in[9];
    const float* Wm3 = (const float*)d_in[10];
    const float* bm3 = (const float*)d_in[11];
    const float* Wl1 = (const float*)d_in[12];
    const float* bl1 = (const float*)d_in[13];
    const float* gl1 = (const float*)d_in[14];
    const float* hl1 = (const float*)d_in[15];
    const float* Wl2 = (const float*)d_in[16];
    const float* bl2 = (const float*)d_in[17];
    const float* gl2 = (const float*)d_in[18];
    const float* hl2 = (const float*)d_in[19];
    const float* Wl3 = (const float*)d_in[20];
    const float* bl3 = (const float*)d_in[21];

    float* out = (float*)d_out;
    float* out_probs = out;
    float* out_mu = out + EE;
    float* out_ls = out + EE + NN * 32;

    float *ax, *raw1, *agg1, *raw2, *y3;
    cudaGetSymbolAddress((void**)&ax, g_ax);
    cudaGetSymbolAddress((void**)&raw1, g_raw1);
    cudaGetSymbolAddress((void**)&agg1, g_agg1);
    cudaGetSymbolAddress((void**)&raw2, g_raw2);
    cudaGetSymbolAddress((void**)&y3, g_y3);

    cudaFuncSetAttribute(k_gemm2, cudaFuncAttributeMaxDynamicSharedMemorySize, 98304);
    cudaFuncSetAttribute(k_gemm3, cudaFuncAttributeMaxDynamicSharedMemorySize, 65536);

    // setup + degree + CSR
    k_zero<<<196, 256>>>();
    k_indeg<<<3125, 256>>>(dst);
    k_dinv<<<196, 256>>>();
    k_scan1<<<49, 1024>>>();
    k_scan2<<<1, 32>>>();
    k_scan3<<<49, 1024>>>();
    k_scatter<<<3125, 256>>>(src, dst);

    // layer 1: aggregate x directly (dinv folded), then fused GEMM + stats
    k_agg1x<<<6250, 256>>>(x, ax);
    k_gemm1<<<782, 256>>>(ax, Wm1, Wl1, bm1, bl1, raw1);
    k_statfin<<<1, 128>>>(0, 128, gm1, hm1, gl1, hl1, 64);

    // layer 2: aggregate raw1 with BN/ReLU on the fly, fused GEMM + stats
    k_agg2bn<<<6250, 256>>>(raw1, agg1);
    k_gemm2<<<782, 256, 98304>>>(agg1, Wm2, Wl2, bm2, bl2, raw2);
    k_statfin<<<1, 256>>>(256, 256, gm2, hm2, gl2, hl2, 128);

    // layer 3: BN-on-load GEMM, final aggregation with epilogue
    k_gemm3<<<391, 256, 65536>>>(raw2, Wm3, Wl3, y3);
    k_agg3f<<<6250, 256>>>(y3, out_mu, bm3, bl3, out_ls);

    // decoder
    k_dec<<<25000, 256>>>(src, dst, out_mu, out_probs);
}

// round 5
// speedup vs baseline: 1.2233x; 1.1424x over previous
#include <cuda_runtime.h>

#define NN 50000
#define EE 800000

typedef unsigned long long ull;

__device__ __forceinline__ void ffma2(ull &d, ull a, ull b) {
    asm("fma.rn.f32x2 %0, %1, %2, %0;" : "+l"(d) : "l"(a), "l"(b));
}
__device__ __forceinline__ ull pack2(float a, float b) {
    ull r; asm("mov.b64 %0, {%1, %2};" : "=l"(r) : "f"(a), "f"(b)); return r;
}
__device__ __forceinline__ float lo2(ull u) { return __uint_as_float((unsigned)u); }
__device__ __forceinline__ float hi2(ull u) { return __uint_as_float((unsigned)(u >> 32)); }

// ---------------- scratch ----------------
__device__ float g_dinv[NN];
__device__ int   g_indeg[NN];
__device__ int   g_cur[NN];
__device__ int   g_off[NN + 1];
__device__ int   g_adj[EE];
__device__ int   g_bsum[64];

__device__ float g_y0[NN * 64];
__device__ float g_ax[NN * 64];
__device__ float g_raw1[NN * 128];
__device__ float g_y1[NN * 128];
__device__ float g_agg1[NN * 128];
__device__ float g_raw2[NN * 256];
__device__ float g_y3[NN * 64];

__device__ float g_ssum[512];
__device__ float g_ssq[512];
__device__ float g_bna[512];
__device__ float g_bnb[512];

// ---------------- setup ----------------
__global__ void k_zero() {
    int i = blockIdx.x * blockDim.x + threadIdx.x;
    if (i < NN) { g_indeg[i] = 0; g_cur[i] = 0; }
    if (i < 512) { g_ssum[i] = 0.f; g_ssq[i] = 0.f; }
}

__global__ void k_indeg(const int* __restrict__ dst) {
    int e = blockIdx.x * blockDim.x + threadIdx.x;
    if (e < EE) atomicAdd(&g_indeg[dst[e]], 1);
}

__global__ void k_dinv_y0(const float* __restrict__ x) {
    int idx = blockIdx.x * blockDim.x + threadIdx.x;
    if (idx < NN * 16) {
        int row = idx >> 4;
        float d = rsqrtf((float)(g_indeg[row] + 1));
        if ((idx & 15) == 0) g_dinv[row] = d;
        float4 v = ((const float4*)x)[idx];
        v.x *= d; v.y *= d; v.z *= d; v.w *= d;
        ((float4*)g_y0)[idx] = v;
    }
}

// ---------------- CSR build ----------------
__global__ void k_scan1() {
    int i = blockIdx.x * 1024 + threadIdx.x;
    int v = (i < NN) ? g_indeg[i] : 0;
    int lane = threadIdx.x & 31, wid = threadIdx.x >> 5;
    int s = v;
    #pragma unroll
    for (int o = 1; o < 32; o <<= 1) {
        int t = __shfl_up_sync(~0u, s, o);
        if (lane >= o) s += t;
    }
    __shared__ int wsum[32];
    if (lane == 31) wsum[wid] = s;
    __syncthreads();
    if (wid == 0) {
        int ws = wsum[lane];
        #pragma unroll
        for (int o = 1; o < 32; o <<= 1) {
            int t = __shfl_up_sync(~0u, ws, o);
            if (lane >= o) ws += t;
        }
        wsum[lane] = ws;
    }
    __syncthreads();
    int incl = s + (wid > 0 ? wsum[wid - 1] : 0);
    if (i < NN) g_off[i + 1] = incl;
    if (threadIdx.x == 1023) g_bsum[blockIdx.x] = incl;
}

__global__ void k_scan2() {
    if (threadIdx.x == 0) {
        int acc = 0;
        for (int b = 0; b < 49; b++) { int t = g_bsum[b]; g_bsum[b] = acc; acc += t; }
    }
}

__global__ void k_scan3() {
    int i = blockIdx.x * 1024 + threadIdx.x;
    if (i < NN) g_off[i + 1] += g_bsum[blockIdx.x];
    if (i == 0) g_off[0] = 0;
}

__global__ void k_scatter(const int* __restrict__ src, const int* __restrict__ dst) {
    int e = blockIdx.x * blockDim.x + threadIdx.x;
    if (e < EE) {
        int d = dst[e];
        int p = g_off[d] + atomicAdd(&g_cur[d], 1);
        g_adj[p] = src[e];
    }
}

// ---------------- aggregation: one warp per node (R2 proven) ----------------
template <int W, int MODE>
__global__ void k_agg(const float* __restrict__ y, float* __restrict__ out,
                      const float* __restrict__ bm3, const float* __restrict__ bl3,
                      float* __restrict__ out_ls) {
    int gw = (blockIdx.x * blockDim.x + threadIdx.x) >> 5;
    if (gw >= NN) return;
    int lane = threadIdx.x & 31;
    int beg = g_off[gw], end = g_off[gw + 1];
    if (W == 64) {
        float2 acc = *(const float2*)(y + gw * 64 + lane * 2);
        for (int j = beg; j < end; j++) {
            int s = g_adj[j];
            float2 v = __ldg((const float2*)(y + s * 64 + lane * 2));
            acc.x += v.x; acc.y += v.y;
        }
        float d = g_dinv[gw];
        acc.x *= d; acc.y *= d;
        if (MODE == 0) {
            *(float2*)(out + gw * 64 + lane * 2) = acc;
        } else {
            int c = lane * 2;
            if (c < 32) {
                out[gw * 32 + c]     = acc.x + bm3[c];
                out[gw * 32 + c + 1] = acc.y + bm3[c + 1];
            } else {
                out_ls[gw * 32 + c - 32] = fminf(acc.x + bl3[c - 32], 10.0f);
                out_ls[gw * 32 + c - 31] = fminf(acc.y + bl3[c - 31], 10.0f);
            }
        }
    } else {
        float4 acc = *(const float4*)(y + gw * 128 + lane * 4);
        for (int j = beg; j < end; j++) {
            int s = g_adj[j];
            float4 v = __ldg((const float4*)(y + s * 128 + lane * 4));
            acc.x += v.x; acc.y += v.y; acc.z += v.z; acc.w += v.w;
        }
        float d = g_dinv[gw];
        acc.x *= d; acc.y *= d; acc.z *= d; acc.w *= d;
        *(float4*)(out + gw * 128 + lane * 4) = acc;
    }
}

// ---------------- layer-1 GEMM: row-pair FFMA2, transposed-A SMEM ----------------
// raw1[:,0:64]=ax@Wm1+bm1, [:,64:128]=ax@Wl1+bl1 + BN stats (cols>=64 relu first)
// dyn smem: Ws 64*128 + Ast 64*66
__global__ void __launch_bounds__(256) k_gemm1(
        const float* __restrict__ A, const float* __restrict__ W1,
        const float* __restrict__ W2, const float* __restrict__ b1,
        const float* __restrict__ b2, float* __restrict__ C) {
    extern __shared__ float sm1[];
    float* Ws  = sm1;          // [k][128]
    float* Ast = sm1 + 8192;   // [k][r] stride 66
    int tid = threadIdx.x;
    int row0 = blockIdx.x * 64;

    for (int i = tid; i < 1024; i += 256) {
        int k = i >> 4, q = i & 15;
        ((float4*)(Ws + k * 128))[q]      = ((const float4*)(W1 + k * 64))[q];
        ((float4*)(Ws + k * 128 + 64))[q] = ((const float4*)(W2 + k * 64))[q];
    }
    for (int i = tid; i < 1024; i += 256) {
        int r = i >> 4, q = i & 15;
        float4 v = make_float4(0.f, 0.f, 0.f, 0.f);
        if (row0 + r < NN) v = ((const float4*)(A + (row0 + r) * 64))[q];
        int k = q * 4;
        Ast[(k + 0) * 66 + r] = v.x;
        Ast[(k + 1) * 66 + r] = v.y;
        Ast[(k + 2) * 66 + r] = v.z;
        Ast[(k + 3) * 66 + r] = v.w;
    }
    __syncthreads();

    int tx = tid & 31, ty = tid >> 5;
    ull acc[4][4];   // [row-pair][col]
    #pragma unroll
    for (int i = 0; i < 4; i++)
        #pragma unroll
        for (int j = 0; j < 4; j++) acc[i][j] = 0ull;

    #pragma unroll 8
    for (int k = 0; k < 64; k++) {
        ull a2[4], w2[4];
        #pragma unroll
        for (int i = 0; i < 4; i++)
            a2[i] = *(const ull*)(Ast + k * 66 + ty * 8 + 2 * i);
        #pragma unroll
        for (int j = 0; j < 4; j++) {
            float w = Ws[k * 128 + tx + 32 * j];
            w2[j] = pack2(w, w);
        }
        #pragma unroll
        for (int i = 0; i < 4; i++)
            #pragma unroll
            for (int j = 0; j < 4; j++)
                ffma2(acc[i][j], a2[i], w2[j]);
    }

    float bb[4];
    bb[0] = b1[tx]; bb[1] = b1[tx + 32]; bb[2] = b2[tx]; bb[3] = b2[tx + 32];

    float ls[4] = {0.f, 0.f, 0.f, 0.f}, l2[4] = {0.f, 0.f, 0.f, 0.f};
    #pragma unroll
    for (int i = 0; i < 4; i++) {
        int r = row0 + ty * 8 + 2 * i;
        #pragma unroll
        for (int h = 0; h < 2; h++) {
            if (r + h < NN) {
                #pragma unroll
                for (int j = 0; j < 4; j++) {
                    float v = (h == 0 ? lo2(acc[i][j]) : hi2(acc[i][j])) + bb[j];
                    C[(size_t)(r + h) * 128 + tx + 32 * j] = v;
                    float sv = (j < 2) ? v : fmaxf(v, 0.f);
                    ls[j] += sv; l2[j] += sv * sv;
                }
            }
        }
    }
    __syncthreads();
    float* red = Ast;
    red[tid] = 0.f;
    __syncthreads();
    #pragma unroll
    for (int j = 0; j < 4; j++) {
        atomicAdd(&red[tx + 32 * j], ls[j]);
        atomicAdd(&red[128 + tx + 32 * j], l2[j]);
    }
    __syncthreads();
    if (tid < 128) {
        atomicAdd(&g_ssum[tid], red[tid]);
        atomicAdd(&g_ssq[tid], red[tid + 128]);
    }
}

__global__ void k_statfin(int base, int C, const float* __restrict__ g1,
                          const float* __restrict__ h1, const float* __restrict__ g2,
                          const float* __restrict__ h2, int half) {
    int c = threadIdx.x;
    if (c < C) {
        float m = g_ssum[base + c] * (1.0f / NN);
        float v = g_ssq[base + c] * (1.0f / NN) - m * m;
        float rstd = rsqrtf(v + 1e-5f);
        float gamma = (c < half) ? g1[c] : g2[c - half];
        float beta  = (c < half) ? h1[c] : h2[c - half];
        float a = gamma * rstd;
        g_bna[base + c] = a;
        g_bnb[base + c] = beta - m * a;
    }
}

__global__ void k_ew1() {
    int idx = blockIdx.x * blockDim.x + threadIdx.x;
    if (idx >= NN * 32) return;
    int r = idx >> 5;
    int c4 = (idx & 31) << 2;
    float4 v = ((const float4*)g_raw1)[idx];
    float d = g_dinv[r];
    float o[4]; float vv[4] = {v.x, v.y, v.z, v.w};
    #pragma unroll
    for (int t = 0; t < 4; t++) {
        int c = c4 + t;
        float a = g_bna[c], b = g_bnb[c];
        if (c4 < 64) o[t] = fmaxf(vv[t] * a + b, 0.f);
        else         o[t] = fmaxf(vv[t], 0.f) * a + b;
        o[t] *= d;
    }
    ((float4*)g_y1)[idx] = make_float4(o[0], o[1], o[2], o[3]);
}

// ---------------- layer-2 GEMM: row-pair FFMA2 ----------------
// raw2[:,0:128]=agg1[:,0:64]@Wm2+bm2; [:,128:256]=agg1[:,64:128]@Wl2+bl2 (+stats)
// dyn smem: Ws 64*256 + Ast 128*66
__global__ void __launch_bounds__(256) k_gemm2(
        const float* __restrict__ A, const float* __restrict__ W1,
        const float* __restrict__ W2, const float* __restrict__ b1,
        const float* __restrict__ b2, float* __restrict__ C) {
    extern __shared__ float sm2[];
    float* Ws  = sm2;            // [k][256], k<64
    float* Ast = sm2 + 16384;    // [k][r] stride 66, k<128
    int tid = threadIdx.x;
    int row0 = blockIdx.x * 64;

    for (int i = tid; i < 2048; i += 256) {
        int k = i >> 5, q = i & 31;
        ((float4*)(Ws + k * 256))[q]       = ((const float4*)(W1 + k * 128))[q];
        ((float4*)(Ws + k * 256 + 128))[q] = ((const float4*)(W2 + k * 128))[q];
    }
    for (int i = tid; i < 2048; i += 256) {
        int r = i >> 5, q = i & 31;
        float4 v = make_float4(0.f, 0.f, 0.f, 0.f);
        if (row0 + r < NN) v = ((const float4*)(A + (size_t)(row0 + r) * 128))[q];
        int k = q * 4;
        Ast[(k + 0) * 66 + r] = v.x;
        Ast[(k + 1) * 66 + r] = v.y;
        Ast[(k + 2) * 66 + r] = v.z;
        Ast[(k + 3) * 66 + r] = v.w;
    }
    __syncthreads();

    int tx = tid & 31, ty = tid >> 5;
    ull acc[4][8];
    #pragma unroll
    for (int i = 0; i < 4; i++)
        #pragma unroll
        for (int j = 0; j < 8; j++) acc[i][j] = 0ull;

    #pragma unroll 4
    for (int k = 0; k < 64; k++) {
        ull alo[4], ahi[4], w2[8];
        #pragma unroll
        for (int i = 0; i < 4; i++) {
            alo[i] = *(const ull*)(Ast + k * 66 + ty * 8 + 2 * i);
            ahi[i] = *(const ull*)(Ast + (64 + k) * 66 + ty * 8 + 2 * i);
        }
        #pragma unroll
        for (int j = 0; j < 8; j++) {
            float w = Ws[k * 256 + tx + 32 * j];
            w2[j] = pack2(w, w);
        }
        #pragma unroll
        for (int i = 0; i < 4; i++)
            #pragma unroll
            for (int j = 0; j < 8; j++)
                ffma2(acc[i][j], (j < 4 ? alo[i] : ahi[i]), w2[j]);
    }

    float bb[8];
    #pragma unroll
    for (int j = 0; j < 8; j++)
        bb[j] = (j < 4) ? b1[tx + 32 * j] : b2[tx + 32 * j - 128];

    float ls[8], l2[8];
    #pragma unroll
    for (int j = 0; j < 8; j++) { ls[j] = 0.f; l2[j] = 0.f; }
    #pragma unroll
    for (int i = 0; i < 4; i++) {
        int r = row0 + ty * 8 + 2 * i;
        #pragma unroll
        for (int h = 0; h < 2; h++) {
            if (r + h < NN) {
                #pragma unroll
                for (int j = 0; j < 8; j++) {
                    float v = (h == 0 ? lo2(acc[i][j]) : hi2(acc[i][j])) + bb[j];
                    C[(size_t)(r + h) * 256 + tx + 32 * j] = v;
                    float sv = (j < 4) ? v : fmaxf(v, 0.f);
                    ls[j] += sv; l2[j] += sv * sv;
                }
            }
        }
    }
    __syncthreads();
    float* red = Ast;
    red[tid] = 0.f; red[tid + 256] = 0.f;
    __syncthreads();
    #pragma unroll
    for (int j = 0; j < 8; j++) {
        atomicAdd(&red[tx + 32 * j], ls[j]);
        atomicAdd(&red[256 + tx + 32 * j], l2[j]);
    }
    __syncthreads();
    atomicAdd(&g_ssum[256 + tid], red[tid]);
    atomicAdd(&g_ssq[256 + tid], red[tid + 256]);
}

// ---------------- layer-3 GEMM with BN-on-load: row-pair FFMA2 ----------------
// dyn smem: Ws 128*64 + Ast 64*130
__global__ void __launch_bounds__(256) k_gemm3(
        const float* __restrict__ raw2, const float* __restrict__ Wm3,
        const float* __restrict__ Wl3, float* __restrict__ y3) {
    extern __shared__ float sm3[];
    float* Ws  = sm3;            // [k][64], k<128
    float* Ast = sm3 + 8192;     // [kk][r] stride 130, kk<64 (per K-tile)
    int tid = threadIdx.x;
    int row0 = blockIdx.x * 128;

    for (int i = tid; i < 2048; i += 256) {
        int k = i >> 4, q = i & 15;
        float4 v = (q < 8) ? ((const float4*)(Wm3 + k * 32))[q]
                           : ((const float4*)(Wl3 + k * 32))[q - 8];
        ((float4*)(Ws + k * 64))[q] = v;
    }

    int tx = tid & 15, ty = tid >> 4;
    int half_c = (tx >= 8) ? 1 : 0;
    ull acc[4][4];
    #pragma unroll
    for (int i = 0; i < 4; i++)
        #pragma unroll
        for (int j = 0; j < 4; j++) acc[i][j] = 0ull;

    for (int kt = 0; kt < 128; kt += 32) {
        __syncthreads();
        for (int i = tid; i < 2048; i += 256) {
            int r = i >> 4, q = i & 15;
            int half = q >> 3, kk = (q & 7) << 2;
            float4 v = make_float4(0.f, 0.f, 0.f, 0.f);
            if (row0 + r < NN)
                v = ((const float4*)(raw2 + (size_t)(row0 + r) * 256 + half * 128 + kt))[q & 7];
            float o[4]; float vv[4] = {v.x, v.y, v.z, v.w};
            #pragma unroll
            for (int t = 0; t < 4; t++) {
                int col = 256 + half * 128 + kt + kk + t;
                float a = g_bna[col], b = g_bnb[col];
                if (half == 0) o[t] = fmaxf(vv[t] * a + b, 0.f);
                else           o[t] = fmaxf(vv[t], 0.f) * a + b;
                Ast[(half * 32 + kk + t) * 130 + r] = o[t];
            }
        }
        __syncthreads();
        #pragma unroll 8
        for (int k = 0; k < 32; k++) {
            float4 w = ((float4*)(Ws + (kt + k) * 64))[tx];
            ull w2[4];
            w2[0] = pack2(w.x, w.x); w2[1] = pack2(w.y, w.y);
            w2[2] = pack2(w.z, w.z); w2[3] = pack2(w.w, w.w);
            ull a2[4];
            #pragma unroll
            for (int i = 0; i < 4; i++)
                a2[i] = *(const ull*)(Ast + (half_c * 32 + k) * 130 + ty * 8 + 2 * i);
            #pragma unroll
            for (int i = 0; i < 4; i++)
                #pragma unroll
                for (int j = 0; j < 4; j++)
                    ffma2(acc[i][j], a2[i], w2[j]);
        }
    }
    #pragma unroll
    for (int i = 0; i < 4; i++) {
        int r = row0 + ty * 8 + 2 * i;
        if (r < NN) {
            float d = g_dinv[r];
            float4 o = make_float4(lo2(acc[i][0]) * d, lo2(acc[i][1]) * d,
                                   lo2(acc[i][2]) * d, lo2(acc[i][3]) * d);
            ((float4*)(y3 + (size_t)r * 64))[tx] = o;
        }
        if (r + 1 < NN) {
            float d = g_dinv[r + 1];
            float4 o = make_float4(hi2(acc[i][0]) * d, hi2(acc[i][1]) * d,
                                   hi2(acc[i][2]) * d, hi2(acc[i][3]) * d);
            ((float4*)(y3 + (size_t)(r + 1) * 64))[tx] = o;
        }
    }
}

// ---------------- decoder ----------------
__global__ void k_dec(const int* __restrict__ src, const int* __restrict__ dst,
                      const float* __restrict__ mu, float* __restrict__ probs) {
    int t = blockIdx.x * blockDim.x + threadIdx.x;
    int e = t >> 3, sub = t & 7;
    int s = src[e], d = dst[e];
    float4 a = __ldg((const float4*)(mu + s * 32 + sub * 4));
    float4 b = __ldg((const float4*)(mu + d * 32 + sub * 4));
    float p = a.x * b.x + a.y * b.y + a.z * b.z + a.w * b.w;
    p += __shfl_down_sync(~0u, p, 4);
    p += __shfl_down_sync(~0u, p, 2);
    p += __shfl_down_sync(~0u, p, 1);
    if (sub == 0) probs[e] = 1.f / (1.f + expf(-p));
}

// ---------------- launch ----------------
extern "C" void kernel_launch(void* const* d_in, const int* in_sizes, int n_in,
                              void* d_out, int out_size) {
    const float* x   = (const float*)d_in[0];
    const int* ei    = (const int*)d_in[1];
    const int* src   = ei;
    const int* dst   = ei + EE;
    const float* Wm1 = (const float*)d_in[2];
    const float* bm1 = (const float*)d_in[3];
    const float* gm1 = (const float*)d_in[4];
    const float* hm1 = (const float*)d_in[5];
    const float* Wm2 = (const float*)d_in[6];
    const float* bm2 = (const float*)d_in[7];
    const float* gm2 = (const float*)d_in[8];
    const float* hm2 = (const float*)d_in[9];
    const float* Wm3 = (const float*)d_in[10];
    const float* bm3 = (const float*)d_in[11];
    const float* Wl1 = (const float*)d_in[12];
    const float* bl1 = (const float*)d_in[13];
    const float* gl1 = (const float*)d_in[14];
    const float* hl1 = (const float*)d_in[15];
    const float* Wl2 = (const float*)d_in[16];
    const float* bl2 = (const float*)d_in[17];
    const float* gl2 = (const float*)d_in[18];
    const float* hl2 = (const float*)d_in[19];
    const float* Wl3 = (const float*)d_in[20];
    const float* bl3 = (const float*)d_in[21];

    float* out = (float*)d_out;
    float* out_probs = out;
    float* out_mu = out + EE;
    float* out_ls = out + EE + NN * 32;

    float *y0, *ax, *raw1, *y1, *agg1, *raw2, *y3;
    cudaGetSymbolAddress((void**)&y0, g_y0);
    cudaGetSymbolAddress((void**)&ax, g_ax);
    cudaGetSymbolAddress((void**)&raw1, g_raw1);
    cudaGetSymbolAddress((void**)&y1, g_y1);
    cudaGetSymbolAddress((void**)&agg1, g_agg1);
    cudaGetSymbolAddress((void**)&raw2, g_raw2);
    cudaGetSymbolAddress((void**)&y3, g_y3);

    const int SM1 = (64 * 128 + 64 * 66) * 4;
    const int SM2 = (64 * 256 + 128 * 66) * 4;
    const int SM3 = (128 * 64 + 64 * 130) * 4;
    cudaFuncSetAttribute(k_gemm1, cudaFuncAttributeMaxDynamicSharedMemorySize, SM1);
    cudaFuncSetAttribute(k_gemm2, cudaFuncAttributeMaxDynamicSharedMemorySize, SM2);
    cudaFuncSetAttribute(k_gemm3, cudaFuncAttributeMaxDynamicSharedMemorySize, SM3);

    // setup + degree + CSR
    k_zero<<<196, 256>>>();
    k_indeg<<<3125, 256>>>(dst);
    k_dinv_y0<<<3125, 256>>>(x);
    k_scan1<<<49, 1024>>>();
    k_scan2<<<1, 32>>>();
    k_scan3<<<49, 1024>>>();
    k_scatter<<<3125, 256>>>(src, dst);

    // layer 1
    k_agg<64, 0><<<6250, 256>>>(y0, ax, nullptr, nullptr, nullptr);
    k_gemm1<<<782, 256, SM1>>>(ax, Wm1, Wl1, bm1, bl1, raw1);
    k_statfin<<<1, 128>>>(0, 128, gm1, hm1, gl1, hl1, 64);
    k_ew1<<<6250, 256>>>();

    // layer 2
    k_agg<128, 0><<<6250, 256>>>(y1, agg1, nullptr, nullptr, nullptr);
    k_gemm2<<<782, 256, SM2>>>(agg1, Wm2, Wl2, bm2, bl2, raw2);
    k_statfin<<<1, 256>>>(256, 256, gm2, hm2, gl2, hl2, 128);

    // layer 3
    k_gemm3<<<391, 256, SM3>>>(raw2, Wm3, Wl3, y3);
    k_agg<64, 1><<<6250, 256>>>(y3, out_mu, bm3, bl3, out_ls);

    // decoder
    k_dec<<<25000, 256>>>(src, dst, out_mu, out_probs);
}

// round 6
// speedup vs baseline: 1.2627x; 1.0323x over previous
#include <cuda_runtime.h>
#include <cuda_fp16.h>

#define NN 50000
#define EE 800000

typedef unsigned long long ull;

__device__ __forceinline__ void ffma2(ull &d, ull a, ull b) {
    asm("fma.rn.f32x2 %0, %1, %2, %0;" : "+l"(d) : "l"(a), "l"(b));
}
__device__ __forceinline__ ull pack2(float a, float b) {
    ull r; asm("mov.b64 %0, {%1, %2};" : "=l"(r) : "f"(a), "f"(b)); return r;
}
__device__ __forceinline__ float lo2(ull u) { return __uint_as_float((unsigned)u); }
__device__ __forceinline__ float hi2(ull u) { return __uint_as_float((unsigned)(u >> 32)); }

// ---------------- scratch ----------------
__device__ float g_dinv[NN];
__device__ int   g_indeg[NN];
__device__ int   g_cur[NN];
__device__ int   g_off[NN + 1];
__device__ int   g_adj[EE];
__device__ int   g_bsum[64];

__device__ __half g_y0h[NN * 64];    // fp16 dinv*x
__device__ float  g_ax[NN * 64];
__device__ float  g_raw1[NN * 128];
__device__ __half g_y1h[NN * 128];   // fp16 dinv*act1
__device__ float  g_agg1[NN * 128];
__device__ float  g_raw2[NN * 256];
__device__ float  g_y3[NN * 64];

__device__ float g_ssum[512];
__device__ float g_ssq[512];
__device__ float g_bna[512];
__device__ float g_bnb[512];

// ---------------- setup ----------------
__global__ void k_zero() {
    int i = blockIdx.x * blockDim.x + threadIdx.x;
    if (i < NN) { g_indeg[i] = 0; g_cur[i] = 0; }
    if (i < 512) { g_ssum[i] = 0.f; g_ssq[i] = 0.f; }
}

__global__ void k_indeg(const int* __restrict__ dst) {
    int e = blockIdx.x * blockDim.x + threadIdx.x;
    if (e < EE) atomicAdd(&g_indeg[dst[e]], 1);
}

// dinv + y0h = half(dinv*x). grid covers NN*16 float4s.
__global__ void k_dinv_y0(const float* __restrict__ x) {
    int idx = blockIdx.x * blockDim.x + threadIdx.x;
    if (idx < NN * 16) {
        int row = idx >> 4;
        float d = rsqrtf((float)(g_indeg[row] + 1));
        if ((idx & 15) == 0) g_dinv[row] = d;
        float4 v = ((const float4*)x)[idx];
        __half2 h0 = __floats2half2_rn(v.x * d, v.y * d);
        __half2 h1 = __floats2half2_rn(v.z * d, v.w * d);
        uint2 o = make_uint2(*(unsigned*)&h0, *(unsigned*)&h1);
        ((uint2*)g_y0h)[idx] = o;
    }
}

// ---------------- CSR build ----------------
__global__ void k_scan1() {
    int i = blockIdx.x * 1024 + threadIdx.x;
    int v = (i < NN) ? g_indeg[i] : 0;
    int lane = threadIdx.x & 31, wid = threadIdx.x >> 5;
    int s = v;
    #pragma unroll
    for (int o = 1; o < 32; o <<= 1) {
        int t = __shfl_up_sync(~0u, s, o);
        if (lane >= o) s += t;
    }
    __shared__ int wsum[32];
    if (lane == 31) wsum[wid] = s;
    __syncthreads();
    if (wid == 0) {
        int ws = wsum[lane];
        #pragma unroll
        for (int o = 1; o < 32; o <<= 1) {
            int t = __shfl_up_sync(~0u, ws, o);
            if (lane >= o) ws += t;
        }
        wsum[lane] = ws;
    }
    __syncthreads();
    int incl = s + (wid > 0 ? wsum[wid - 1] : 0);
    if (i < NN) g_off[i + 1] = incl;
    if (threadIdx.x == 1023) g_bsum[blockIdx.x] = incl;
}

// block-total prefix folded in (removes separate serial kernel)
__global__ void k_scan3() {
    __shared__ int base;
    if (threadIdx.x == 0) {
        int acc = 0;
        for (int b = 0; b < blockIdx.x; b++) acc += g_bsum[b];
        base = acc;
    }
    __syncthreads();
    int i = blockIdx.x * 1024 + threadIdx.x;
    if (i < NN) g_off[i + 1] += base;
    if (i == 0) g_off[0] = 0;
}

__global__ void k_scatter(const int* __restrict__ src, const int* __restrict__ dst) {
    int e = blockIdx.x * blockDim.x + threadIdx.x;
    if (e < EE) {
        int d = dst[e];
        int p = g_off[d] + atomicAdd(&g_cur[d], 1);
        g_adj[p] = src[e];
    }
}

// ---------------- layer-1 aggregation: fp16 gather, fp32 accumulate ----------------
__global__ void k_agg1h(const __half* __restrict__ y, float* __restrict__ out) {
    int gw = (blockIdx.x * blockDim.x + threadIdx.x) >> 5;
    if (gw >= NN) return;
    int lane = threadIdx.x & 31;
    int beg = g_off[gw], end = g_off[gw + 1];
    float2 acc = __half22float2(*(const __half2*)(y + gw * 64 + lane * 2));
    for (int j = beg; j < end; j++) {
        int s = g_adj[j];
        float2 v = __half22float2(__ldg((const __half2*)(y + s * 64 + lane * 2)));
        acc.x += v.x; acc.y += v.y;
    }
    float d = g_dinv[gw];
    acc.x *= d; acc.y *= d;
    *(float2*)(out + gw * 64 + lane * 2) = acc;
}

// ---------------- layer-2 aggregation: fp16 gather (4 cols/lane) ----------------
__global__ void k_agg2h(const __half* __restrict__ y, float* __restrict__ out) {
    int gw = (blockIdx.x * blockDim.x + threadIdx.x) >> 5;
    if (gw >= NN) return;
    int lane = threadIdx.x & 31;
    int beg = g_off[gw], end = g_off[gw + 1];
    uint2 u0 = *(const uint2*)(y + (size_t)gw * 128 + lane * 4);
    float2 a01 = __half22float2(*(__half2*)&u0.x);
    float2 a23 = __half22float2(*(__half2*)&u0.y);
    float4 acc = make_float4(a01.x, a01.y, a23.x, a23.y);
    for (int j = beg; j < end; j++) {
        int s = g_adj[j];
        uint2 u = __ldg((const uint2*)(y + (size_t)s * 128 + lane * 4));
        float2 f01 = __half22float2(*(__half2*)&u.x);
        float2 f23 = __half22float2(*(__half2*)&u.y);
        acc.x += f01.x; acc.y += f01.y; acc.z += f23.x; acc.w += f23.y;
    }
    float d = g_dinv[gw];
    acc.x *= d; acc.y *= d; acc.z *= d; acc.w *= d;
    *(float4*)(out + (size_t)gw * 128 + lane * 4) = acc;
}

// ---------------- layer-3 aggregation (fp32) + final epilogue ----------------
__global__ void k_agg3f(const float* __restrict__ y, float* __restrict__ out_mu,
                        const float* __restrict__ bm3, const float* __restrict__ bl3,
                        float* __restrict__ out_ls) {
    int gw = (blockIdx.x * blockDim.x + threadIdx.x) >> 5;
    if (gw >= NN) return;
    int lane = threadIdx.x & 31;
    int beg = g_off[gw], end = g_off[gw + 1];
    float2 acc = *(const float2*)(y + gw * 64 + lane * 2);
    for (int j = beg; j < end; j++) {
        int s = g_adj[j];
        float2 v = __ldg((const float2*)(y + s * 64 + lane * 2));
        acc.x += v.x; acc.y += v.y;
    }
    float d = g_dinv[gw];
    acc.x *= d; acc.y *= d;
    int c = lane * 2;
    if (c < 32) {
        out_mu[gw * 32 + c]     = acc.x + bm3[c];
        out_mu[gw * 32 + c + 1] = acc.y + bm3[c + 1];
    } else {
        out_ls[gw * 32 + c - 32] = fminf(acc.x + bl3[c - 32], 10.0f);
        out_ls[gw * 32 + c - 31] = fminf(acc.y + bl3[c - 31], 10.0f);
    }
}

// ---------------- layer-1 GEMM: row-pair FFMA2 (R5 proven) ----------------
__global__ void __launch_bounds__(256) k_gemm1(
        const float* __restrict__ A, const float* __restrict__ W1,
        const float* __restrict__ W2, const float* __restrict__ b1,
        const float* __restrict__ b2, float* __restrict__ C) {
    extern __shared__ float sm1[];
    float* Ws  = sm1;
    float* Ast = sm1 + 8192;
    int tid = threadIdx.x;
    int row0 = blockIdx.x * 64;

    for (int i = tid; i < 1024; i += 256) {
        int k = i >> 4, q = i & 15;
        ((float4*)(Ws + k * 128))[q]      = ((const float4*)(W1 + k * 64))[q];
        ((float4*)(Ws + k * 128 + 64))[q] = ((const float4*)(W2 + k * 64))[q];
    }
    for (int i = tid; i < 1024; i += 256) {
        int r = i >> 4, q = i & 15;
        float4 v = make_float4(0.f, 0.f, 0.f, 0.f);
        if (row0 + r < NN) v = ((const float4*)(A + (row0 + r) * 64))[q];
        int k = q * 4;
        Ast[(k + 0) * 66 + r] = v.x;
        Ast[(k + 1) * 66 + r] = v.y;
        Ast[(k + 2) * 66 + r] = v.z;
        Ast[(k + 3) * 66 + r] = v.w;
    }
    __syncthreads();

    int tx = tid & 31, ty = tid >> 5;
    ull acc[4][4];
    #pragma unroll
    for (int i = 0; i < 4; i++)
        #pragma unroll
        for (int j = 0; j < 4; j++) acc[i][j] = 0ull;

    #pragma unroll 8
    for (int k = 0; k < 64; k++) {
        ull a2[4], w2[4];
        #pragma unroll
        for (int i = 0; i < 4; i++)
            a2[i] = *(const ull*)(Ast + k * 66 + ty * 8 + 2 * i);
        #pragma unroll
        for (int j = 0; j < 4; j++) {
            float w = Ws[k * 128 + tx + 32 * j];
            w2[j] = pack2(w, w);
        }
        #pragma unroll
        for (int i = 0; i < 4; i++)
            #pragma unroll
            for (int j = 0; j < 4; j++)
                ffma2(acc[i][j], a2[i], w2[j]);
    }

    float bb[4];
    bb[0] = b1[tx]; bb[1] = b1[tx + 32]; bb[2] = b2[tx]; bb[3] = b2[tx + 32];

    float ls[4] = {0.f, 0.f, 0.f, 0.f}, l2[4] = {0.f, 0.f, 0.f, 0.f};
    #pragma unroll
    for (int i = 0; i < 4; i++) {
        int r = row0 + ty * 8 + 2 * i;
        #pragma unroll
        for (int h = 0; h < 2; h++) {
            if (r + h < NN) {
                #pragma unroll
                for (int j = 0; j < 4; j++) {
                    float v = (h == 0 ? lo2(acc[i][j]) : hi2(acc[i][j])) + bb[j];
                    C[(size_t)(r + h) * 128 + tx + 32 * j] = v;
                    float sv = (j < 2) ? v : fmaxf(v, 0.f);
                    ls[j] += sv; l2[j] += sv * sv;
                }
            }
        }
    }
    __syncthreads();
    float* red = Ast;
    red[tid] = 0.f;
    __syncthreads();
    #pragma unroll
    for (int j = 0; j < 4; j++) {
        atomicAdd(&red[tx + 32 * j], ls[j]);
        atomicAdd(&red[128 + tx + 32 * j], l2[j]);
    }
    __syncthreads();
    if (tid < 128) {
        atomicAdd(&g_ssum[tid], red[tid]);
        atomicAdd(&g_ssq[tid], red[tid + 128]);
    }
}

__global__ void k_statfin(int base, int C, const float* __restrict__ g1,
                          const float* __restrict__ h1, const float* __restrict__ g2,
                          const float* __restrict__ h2, int half) {
    int c = threadIdx.x;
    if (c < C) {
        float m = g_ssum[base + c] * (1.0f / NN);
        float v = g_ssq[base + c] * (1.0f / NN) - m * m;
        float rstd = rsqrtf(v + 1e-5f);
        float gamma = (c < half) ? g1[c] : g2[c - half];
        float beta  = (c < half) ? h1[c] : h2[c - half];
        float a = gamma * rstd;
        g_bna[base + c] = a;
        g_bnb[base + c] = beta - m * a;
    }
}

// elementwise layer1 -> fp16 y1h
__global__ void k_ew1() {
    int idx = blockIdx.x * blockDim.x + threadIdx.x;
    if (idx >= NN * 32) return;
    int r = idx >> 5;
    int c4 = (idx & 31) << 2;
    float4 v = ((const float4*)g_raw1)[idx];
    float d = g_dinv[r];
    float o[4]; float vv[4] = {v.x, v.y, v.z, v.w};
    #pragma unroll
    for (int t = 0; t < 4; t++) {
        int c = c4 + t;
        float a = g_bna[c], b = g_bnb[c];
        if (c4 < 64) o[t] = fmaxf(vv[t] * a + b, 0.f);
        else         o[t] = fmaxf(vv[t], 0.f) * a + b;
        o[t] *= d;
    }
    __half2 h0 = __floats2half2_rn(o[0], o[1]);
    __half2 h1 = __floats2half2_rn(o[2], o[3]);
    ((uint2*)g_y1h)[idx] = make_uint2(*(unsigned*)&h0, *(unsigned*)&h1);
}

// ---------------- layer-2 GEMM: row-pair FFMA2 (R5 proven) ----------------
__global__ void __launch_bounds__(256) k_gemm2(
        const float* __restrict__ A, const float* __restrict__ W1,
        const float* __restrict__ W2, const float* __restrict__ b1,
        const float* __restrict__ b2, float* __restrict__ C) {
    extern __shared__ float sm2[];
    float* Ws  = sm2;
    float* Ast = sm2 + 16384;
    int tid = threadIdx.x;
    int row0 = blockIdx.x * 64;

    for (int i = tid; i < 2048; i += 256) {
        int k = i >> 5, q = i & 31;
        ((float4*)(Ws + k * 256))[q]       = ((const float4*)(W1 + k * 128))[q];
        ((float4*)(Ws + k * 256 + 128))[q] = ((const float4*)(W2 + k * 128))[q];
    }
    for (int i = tid; i < 2048; i += 256) {
        int r = i >> 5, q = i & 31;
        float4 v = make_float4(0.f, 0.f, 0.f, 0.f);
        if (row0 + r < NN) v = ((const float4*)(A + (size_t)(row0 + r) * 128))[q];
        int k = q * 4;
        Ast[(k + 0) * 66 + r] = v.x;
        Ast[(k + 1) * 66 + r] = v.y;
        Ast[(k + 2) * 66 + r] = v.z;
        Ast[(k + 3) * 66 + r] = v.w;
    }
    __syncthreads();

    int tx = tid & 31, ty = tid >> 5;
    ull acc[4][8];
    #pragma unroll
    for (int i = 0; i < 4; i++)
        #pragma unroll
        for (int j = 0; j < 8; j++) acc[i][j] = 0ull;

    #pragma unroll 4
    for (int k = 0; k < 64; k++) {
        ull alo[4], ahi[4], w2[8];
        #pragma unroll
        for (int i = 0; i < 4; i++) {
            alo[i] = *(const ull*)(Ast + k * 66 + ty * 8 + 2 * i);
            ahi[i] = *(const ull*)(Ast + (64 + k) * 66 + ty * 8 + 2 * i);
        }
        #pragma unroll
        for (int j = 0; j < 8; j++) {
            float w = Ws[k * 256 + tx + 32 * j];
            w2[j] = pack2(w, w);
        }
        #pragma unroll
        for (int i = 0; i < 4; i++)
            #pragma unroll
            for (int j = 0; j < 8; j++)
                ffma2(acc[i][j], (j < 4 ? alo[i] : ahi[i]), w2[j]);
    }

    float bb[8];
    #pragma unroll
    for (int j = 0; j < 8; j++)
        bb[j] = (j < 4) ? b1[tx + 32 * j] : b2[tx + 32 * j - 128];

    float ls[8], l2[8];
    #pragma unroll
    for (int j = 0; j < 8; j++) { ls[j] = 0.f; l2[j] = 0.f; }
    #pragma unroll
    for (int i = 0; i < 4; i++) {
        int r = row0 + ty * 8 + 2 * i;
        #pragma unroll
        for (int h = 0; h < 2; h++) {
            if (r + h < NN) {
                #pragma unroll
                for (int j = 0; j < 8; j++) {
                    float v = (h == 0 ? lo2(acc[i][j]) : hi2(acc[i][j])) + bb[j];
                    C[(size_t)(r + h) * 256 + tx + 32 * j] = v;
                    float sv = (j < 4) ? v : fmaxf(v, 0.f);
                    ls[j] += sv; l2[j] += sv * sv;
                }
            }
        }
    }
    __syncthreads();
    float* red = Ast;
    red[tid] = 0.f; red[tid + 256] = 0.f;
    __syncthreads();
    #pragma unroll
    for (int j = 0; j < 8; j++) {
        atomicAdd(&red[tx + 32 * j], ls[j]);
        atomicAdd(&red[256 + tx + 32 * j], l2[j]);
    }
    __syncthreads();
    atomicAdd(&g_ssum[256 + tid], red[tid]);
    atomicAdd(&g_ssq[256 + tid], red[tid + 256]);
}

// ---------------- layer-3 GEMM with BN-on-load: row-pair FFMA2 (R5 proven) ----------------
__global__ void __launch_bounds__(256) k_gemm3(
        const float* __restrict__ raw2, const float* __restrict__ Wm3,
        const float* __restrict__ Wl3, float* __restrict__ y3) {
    extern __shared__ float sm3[];
    float* Ws  = sm3;
    float* Ast = sm3 + 8192;
    int tid = threadIdx.x;
    int row0 = blockIdx.x * 128;

    for (int i = tid; i < 2048; i += 256) {
        int k = i >> 4, q = i & 15;
        float4 v = (q < 8) ? ((const float4*)(Wm3 + k * 32))[q]
                           : ((const float4*)(Wl3 + k * 32))[q - 8];
        ((float4*)(Ws + k * 64))[q] = v;
    }

    int tx = tid & 15, ty = tid >> 4;
    int half_c = (tx >= 8) ? 1 : 0;
    ull acc[4][4];
    #pragma unroll
    for (int i = 0; i < 4; i++)
        #pragma unroll
        for (int j = 0; j < 4; j++) acc[i][j] = 0ull;

    for (int kt = 0; kt < 128; kt += 32) {
        __syncthreads();
        for (int i = tid; i < 2048; i += 256) {
            int r = i >> 4, q = i & 15;
            int half = q >> 3, kk = (q & 7) << 2;
            float4 v = make_float4(0.f, 0.f, 0.f, 0.f);
            if (row0 + r < NN)
                v = ((const float4*)(raw2 + (size_t)(row0 + r) * 256 + half * 128 + kt))[q & 7];
            float o[4]; float vv[4] = {v.x, v.y, v.z, v.w};
            #pragma unroll
            for (int t = 0; t < 4; t++) {
                int col = 256 + half * 128 + kt + kk + t;
                float a = g_bna[col], b = g_bnb[col];
                if (half == 0) o[t] = fmaxf(vv[t] * a + b, 0.f);
                else           o[t] = fmaxf(vv[t], 0.f) * a + b;
                Ast[(half * 32 + kk + t) * 130 + r] = o[t];
            }
        }
        __syncthreads();
        #pragma unroll 8
        for (int k = 0; k < 32; k++) {
            float4 w = ((float4*)(Ws + (kt + k) * 64))[tx];
            ull w2[4];
            w2[0] = pack2(w.x, w.x); w2[1] = pack2(w.y, w.y);
            w2[2] = pack2(w.z, w.z); w2[3] = pack2(w.w, w.w);
            ull a2[4];
            #pragma unroll
            for (int i = 0; i < 4; i++)
                a2[i] = *(const ull*)(Ast + (half_c * 32 + k) * 130 + ty * 8 + 2 * i);
            #pragma unroll
            for (int i = 0; i < 4; i++)
                #pragma unroll
                for (int j = 0; j < 4; j++)
                    ffma2(acc[i][j], a2[i], w2[j]);
        }
    }
    #pragma unroll
    for (int i = 0; i < 4; i++) {
        int r = row0 + ty * 8 + 2 * i;
        if (r < NN) {
            float d = g_dinv[r];
            float4 o = make_float4(lo2(acc[i][0]) * d, lo2(acc[i][1]) * d,
                                   lo2(acc[i][2]) * d, lo2(acc[i][3]) * d);
            ((float4*)(y3 + (size_t)r * 64))[tx] = o;
        }
        if (r + 1 < NN) {
            float d = g_dinv[r + 1];
            float4 o = make_float4(hi2(acc[i][0]) * d, hi2(acc[i][1]) * d,
                                   hi2(acc[i][2]) * d, hi2(acc[i][3]) * d);
            ((float4*)(y3 + (size_t)(r + 1) * 64))[tx] = o;
        }
    }
}

// ---------------- decoder ----------------
__global__ void k_dec(const int* __restrict__ src, const int* __restrict__ dst,
                      const float* __restrict__ mu, float* __restrict__ probs) {
    int t = blockIdx.x * blockDim.x + threadIdx.x;
    int e = t >> 3, sub = t & 7;
    int s = src[e], d = dst[e];
    float4 a = __ldg((const float4*)(mu + s * 32 + sub * 4));
    float4 b = __ldg((const float4*)(mu + d * 32 + sub * 4));
    float p = a.x * b.x + a.y * b.y + a.z * b.z + a.w * b.w;
    p += __shfl_down_sync(~0u, p, 4);
    p += __shfl_down_sync(~0u, p, 2);
    p += __shfl_down_sync(~0u, p, 1);
    if (sub == 0) probs[e] = 1.f / (1.f + expf(-p));
}

// ---------------- launch ----------------
extern "C" void kernel_launch(void* const* d_in, const int* in_sizes, int n_in,
                              void* d_out, int out_size) {
    const float* x   = (const float*)d_in[0];
    const int* ei    = (const int*)d_in[1];
    const int* src   = ei;
    const int* dst   = ei + EE;
    const float* Wm1 = (const float*)d_in[2];
    const float* bm1 = (const float*)d_in[3];
    const float* gm1 = (const float*)d_in[4];
    const float* hm1 = (const float*)d_in[5];
    const float* Wm2 = (const float*)d_in[6];
    const float* bm2 = (const float*)d_in[7];
    const float* gm2 = (const float*)d_in[8];
    const float* hm2 = (const float*)d_in[9];
    const float* Wm3 = (const float*)d_in[10];
    const float* bm3 = (const float*)d_in[11];
    const float* Wl1 = (const float*)d_in[12];
    const float* bl1 = (const float*)d_in[13];
    const float* gl1 = (const float*)d_in[14];
    const float* hl1 = (const float*)d_in[15];
    const float* Wl2 = (const float*)d_in[16];
    const float* bl2 = (const float*)d_in[17];
    const float* gl2 = (const float*)d_in[18];
    const float* hl2 = (const float*)d_in[19];
    const float* Wl3 = (const float*)d_in[20];
    const float* bl3 = (const float*)d_in[21];

    float* out = (float*)d_out;
    float* out_probs = out;
    float* out_mu = out + EE;
    float* out_ls = out + EE + NN * 32;

    float *ax, *raw1, *agg1, *raw2, *y3;
    __half *y0h, *y1h;
    cudaGetSymbolAddress((void**)&y0h, g_y0h);
    cudaGetSymbolAddress((void**)&ax, g_ax);
    cudaGetSymbolAddress((void**)&raw1, g_raw1);
    cudaGetSymbolAddress((void**)&y1h, g_y1h);
    cudaGetSymbolAddress((void**)&agg1, g_agg1);
    cudaGetSymbolAddress((void**)&raw2, g_raw2);
    cudaGetSymbolAddress((void**)&y3, g_y3);

    const int SM1 = (64 * 128 + 64 * 66) * 4;
    const int SM2 = (64 * 256 + 128 * 66) * 4;
    const int SM3 = (128 * 64 + 64 * 130) * 4;
    cudaFuncSetAttribute(k_gemm1, cudaFuncAttributeMaxDynamicSharedMemorySize, SM1);
    cudaFuncSetAttribute(k_gemm2, cudaFuncAttributeMaxDynamicSharedMemorySize, SM2);
    cudaFuncSetAttribute(k_gemm3, cudaFuncAttributeMaxDynamicSharedMemorySize, SM3);

    // setup + degree + CSR
    k_zero<<<196, 256>>>();
    k_indeg<<<3125, 256>>>(dst);
    k_dinv_y0<<<3125, 256>>>(x);
    k_scan1<<<49, 1024>>>();
    k_scan3<<<49, 1024>>>();
    k_scatter<<<3125, 256>>>(src, dst);

    // layer 1
    k_agg1h<<<6250, 256>>>(y0h, ax);
    k_gemm1<<<782, 256, SM1>>>(ax, Wm1, Wl1, bm1, bl1, raw1);
    k_statfin<<<1, 128>>>(0, 128, gm1, hm1, gl1, hl1, 64);
    k_ew1<<<6250, 256>>>();

    // layer 2
    k_agg2h<<<6250, 256>>>(y1h, agg1);
    k_gemm2<<<782, 256, SM2>>>(agg1, Wm2, Wl2, bm2, bl2, raw2);
    k_statfin<<<1, 256>>>(256, 256, gm2, hm2, gl2, hl2, 128);

    // layer 3
    k_gemm3<<<391, 256, SM3>>>(raw2, Wm3, Wl3, y3);
    k_agg3f<<<6250, 256>>>(y3, out_mu, bm3, bl3, out_ls);

    // decoder
    k_dec<<<25000, 256>>>(src, dst, out_mu, out_probs);
}

// round 7
// speedup vs baseline: 1.2753x; 1.0100x over previous
#include <cuda_runtime.h>
#include <cuda_fp16.h>

#define NN 50000
#define EE 800000

typedef unsigned long long ull;

__device__ __forceinline__ void ffma2(ull &d, ull a, ull b) {
    asm("fma.rn.f32x2 %0, %1, %2, %0;" : "+l"(d) : "l"(a), "l"(b));
}
__device__ __forceinline__ ull pack2(float a, float b) {
    ull r; asm("mov.b64 %0, {%1, %2};" : "=l"(r) : "f"(a), "f"(b)); return r;
}
__device__ __forceinline__ float lo2(ull u) { return __uint_as_float((unsigned)u); }
__device__ __forceinline__ float hi2(ull u) { return __uint_as_float((unsigned)(u >> 32)); }

// ---------------- scratch ----------------
__device__ float g_dinv[NN];
__device__ int   g_indeg[NN];
__device__ int   g_cur[NN];
__device__ int   g_off[NN + 1];
__device__ int   g_adj[EE];
__device__ int   g_bsum[64];

__device__ __half g_y0h[NN * 64];    // fp16 dinv*x
__device__ float  g_ax[NN * 64];
__device__ float  g_raw1[NN * 128];
__device__ __half g_y1h[NN * 128];   // fp16 dinv*act1
__device__ float  g_agg1[NN * 128];
__device__ float  g_raw2[NN * 256];
__device__ __half g_y3h[NN * 64];    // fp16 dinv*(act2@W3)

__device__ float g_ssum[512];
__device__ float g_ssq[512];

// ---------------- setup ----------------
__global__ void k_zero() {
    int i = blockIdx.x * blockDim.x + threadIdx.x;
    if (i < NN) { g_indeg[i] = 0; g_cur[i] = 0; }
    if (i < 512) { g_ssum[i] = 0.f; g_ssq[i] = 0.f; }
}

__global__ void k_indeg(const int* __restrict__ dst) {
    int e = blockIdx.x * blockDim.x + threadIdx.x;
    if (e < EE) atomicAdd(&g_indeg[dst[e]], 1);
}

__global__ void k_dinv_y0(const float* __restrict__ x) {
    int idx = blockIdx.x * blockDim.x + threadIdx.x;
    if (idx < NN * 16) {
        int row = idx >> 4;
        float d = rsqrtf((float)(g_indeg[row] + 1));
        if ((idx & 15) == 0) g_dinv[row] = d;
        float4 v = ((const float4*)x)[idx];
        __half2 h0 = __floats2half2_rn(v.x * d, v.y * d);
        __half2 h1 = __floats2half2_rn(v.z * d, v.w * d);
        ((uint2*)g_y0h)[idx] = make_uint2(*(unsigned*)&h0, *(unsigned*)&h1);
    }
}

// ---------------- CSR build ----------------
__global__ void k_scan1() {
    int i = blockIdx.x * 1024 + threadIdx.x;
    int v = (i < NN) ? g_indeg[i] : 0;
    int lane = threadIdx.x & 31, wid = threadIdx.x >> 5;
    int s = v;
    #pragma unroll
    for (int o = 1; o < 32; o <<= 1) {
        int t = __shfl_up_sync(~0u, s, o);
        if (lane >= o) s += t;
    }
    __shared__ int wsum[32];
    if (lane == 31) wsum[wid] = s;
    __syncthreads();
    if (wid == 0) {
        int ws = wsum[lane];
        #pragma unroll
        for (int o = 1; o < 32; o <<= 1) {
            int t = __shfl_up_sync(~0u, ws, o);
            if (lane >= o) ws += t;
        }
        wsum[lane] = ws;
    }
    __syncthreads();
    int incl = s + (wid > 0 ? wsum[wid - 1] : 0);
    if (i < NN) g_off[i + 1] = incl;
    if (threadIdx.x == 1023) g_bsum[blockIdx.x] = incl;
}

__global__ void k_scan3() {
    __shared__ int base;
    if (threadIdx.x == 0) {
        int acc = 0;
        for (int b = 0; b < blockIdx.x; b++) acc += g_bsum[b];
        base = acc;
    }
    __syncthreads();
    int i = blockIdx.x * 1024 + threadIdx.x;
    if (i < NN) g_off[i + 1] += base;
    if (i == 0) g_off[0] = 0;
}

__global__ void k_scatter(const int* __restrict__ src, const int* __restrict__ dst) {
    int e = blockIdx.x * blockDim.x + threadIdx.x;
    if (e < EE) {
        int d = dst[e];
        int p = g_off[d] + atomicAdd(&g_cur[d], 1);
        g_adj[p] = src[e];
    }
}

// ---------------- layer-1 aggregation: fp16 gather, fp32 accumulate ----------------
__global__ void k_agg1h(const __half* __restrict__ y, float* __restrict__ out) {
    int gw = (blockIdx.x * blockDim.x + threadIdx.x) >> 5;
    if (gw >= NN) return;
    int lane = threadIdx.x & 31;
    int beg = g_off[gw], end = g_off[gw + 1];
    float2 acc = __half22float2(*(const __half2*)(y + gw * 64 + lane * 2));
    for (int j = beg; j < end; j++) {
        int s = g_adj[j];
        float2 v = __half22float2(__ldg((const __half2*)(y + s * 64 + lane * 2)));
        acc.x += v.x; acc.y += v.y;
    }
    float d = g_dinv[gw];
    acc.x *= d; acc.y *= d;
    *(float2*)(out + gw * 64 + lane * 2) = acc;
}

// ---------------- layer-2 aggregation: fp16 gather (4 cols/lane) ----------------
__global__ void k_agg2h(const __half* __restrict__ y, float* __restrict__ out) {
    int gw = (blockIdx.x * blockDim.x + threadIdx.x) >> 5;
    if (gw >= NN) return;
    int lane = threadIdx.x & 31;
    int beg = g_off[gw], end = g_off[gw + 1];
    uint2 u0 = *(const uint2*)(y + (size_t)gw * 128 + lane * 4);
    float2 a01 = __half22float2(*(__half2*)&u0.x);
    float2 a23 = __half22float2(*(__half2*)&u0.y);
    float4 acc = make_float4(a01.x, a01.y, a23.x, a23.y);
    for (int j = beg; j < end; j++) {
        int s = g_adj[j];
        uint2 u = __ldg((const uint2*)(y + (size_t)s * 128 + lane * 4));
        float2 f01 = __half22float2(*(__half2*)&u.x);
        float2 f23 = __half22float2(*(__half2*)&u.y);
        acc.x += f01.x; acc.y += f01.y; acc.z += f23.x; acc.w += f23.y;
    }
    float d = g_dinv[gw];
    acc.x *= d; acc.y *= d; acc.z *= d; acc.w *= d;
    *(float4*)(out + (size_t)gw * 128 + lane * 4) = acc;
}

// ---------------- layer-3 aggregation (fp16 gather) + final epilogue ----------------
__global__ void k_agg3f(const __half* __restrict__ y, float* __restrict__ out_mu,
                        const float* __restrict__ bm3, const float* __restrict__ bl3,
                        float* __restrict__ out_ls) {
    int gw = (blockIdx.x * blockDim.x + threadIdx.x) >> 5;
    if (gw >= NN) return;
    int lane = threadIdx.x & 31;
    int beg = g_off[gw], end = g_off[gw + 1];
    float2 acc = __half22float2(*(const __half2*)(y + gw * 64 + lane * 2));
    for (int j = beg; j < end; j++) {
        int s = g_adj[j];
        float2 v = __half22float2(__ldg((const __half2*)(y + s * 64 + lane * 2)));
        acc.x += v.x; acc.y += v.y;
    }
    float d = g_dinv[gw];
    acc.x *= d; acc.y *= d;
    int c = lane * 2;
    if (c < 32) {
        out_mu[gw * 32 + c]     = acc.x + bm3[c];
        out_mu[gw * 32 + c + 1] = acc.y + bm3[c + 1];
    } else {
        out_ls[gw * 32 + c - 32] = fminf(acc.x + bl3[c - 32], 10.0f);
        out_ls[gw * 32 + c - 31] = fminf(acc.y + bl3[c - 31], 10.0f);
    }
}

// ---------------- layer-1 GEMM: row-pair FFMA2 ----------------
__global__ void __launch_bounds__(256) k_gemm1(
        const float* __restrict__ A, const float* __restrict__ W1,
        const float* __restrict__ W2, const float* __restrict__ b1,
        const float* __restrict__ b2, float* __restrict__ C) {
    extern __shared__ float sm1[];
    float* Ws  = sm1;
    float* Ast = sm1 + 8192;
    int tid = threadIdx.x;
    int row0 = blockIdx.x * 64;

    for (int i = tid; i < 1024; i += 256) {
        int k = i >> 4, q = i & 15;
        ((float4*)(Ws + k * 128))[q]      = ((const float4*)(W1 + k * 64))[q];
        ((float4*)(Ws + k * 128 + 64))[q] = ((const float4*)(W2 + k * 64))[q];
    }
    for (int i = tid; i < 1024; i += 256) {
        int r = i >> 4, q = i & 15;
        float4 v = make_float4(0.f, 0.f, 0.f, 0.f);
        if (row0 + r < NN) v = ((const float4*)(A + (row0 + r) * 64))[q];
        int k = q * 4;
        Ast[(k + 0) * 66 + r] = v.x;
        Ast[(k + 1) * 66 + r] = v.y;
        Ast[(k + 2) * 66 + r] = v.z;
        Ast[(k + 3) * 66 + r] = v.w;
    }
    __syncthreads();

    int tx = tid & 31, ty = tid >> 5;
    ull acc[4][4];
    #pragma unroll
    for (int i = 0; i < 4; i++)
        #pragma unroll
        for (int j = 0; j < 4; j++) acc[i][j] = 0ull;

    #pragma unroll 8
    for (int k = 0; k < 64; k++) {
        ull a2[4], w2[4];
        #pragma unroll
        for (int i = 0; i < 4; i++)
            a2[i] = *(const ull*)(Ast + k * 66 + ty * 8 + 2 * i);
        #pragma unroll
        for (int j = 0; j < 4; j++) {
            float w = Ws[k * 128 + tx + 32 * j];
            w2[j] = pack2(w, w);
        }
        #pragma unroll
        for (int i = 0; i < 4; i++)
            #pragma unroll
            for (int j = 0; j < 4; j++)
                ffma2(acc[i][j], a2[i], w2[j]);
    }

    float bb[4];
    bb[0] = b1[tx]; bb[1] = b1[tx + 32]; bb[2] = b2[tx]; bb[3] = b2[tx + 32];

    float ls[4] = {0.f, 0.f, 0.f, 0.f}, l2[4] = {0.f, 0.f, 0.f, 0.f};
    #pragma unroll
    for (int i = 0; i < 4; i++) {
        int r = row0 + ty * 8 + 2 * i;
        #pragma unroll
        for (int h = 0; h < 2; h++) {
            if (r + h < NN) {
                #pragma unroll
                for (int j = 0; j < 4; j++) {
                    float v = (h == 0 ? lo2(acc[i][j]) : hi2(acc[i][j])) + bb[j];
                    C[(size_t)(r + h) * 128 + tx + 32 * j] = v;
                    float sv = (j < 2) ? v : fmaxf(v, 0.f);
                    ls[j] += sv; l2[j] += sv * sv;
                }
            }
        }
    }
    __syncthreads();
    float* red = Ast;
    red[tid] = 0.f;
    __syncthreads();
    #pragma unroll
    for (int j = 0; j < 4; j++) {
        atomicAdd(&red[tx + 32 * j], ls[j]);
        atomicAdd(&red[128 + tx + 32 * j], l2[j]);
    }
    __syncthreads();
    if (tid < 128) {
        atomicAdd(&g_ssum[tid], red[tid]);
        atomicAdd(&g_ssq[tid], red[tid + 128]);
    }
}

// elementwise layer1 -> fp16 y1h, with statfin folded in (per-block affine compute)
__global__ void k_ew1(const float* __restrict__ g1, const float* __restrict__ h1,
                      const float* __restrict__ g2, const float* __restrict__ h2) {
    __shared__ float sa[128], sb[128];
    int tid = threadIdx.x;
    if (tid < 128) {
        float m = g_ssum[tid] * (1.0f / NN);
        float v = g_ssq[tid] * (1.0f / NN) - m * m;
        float rstd = rsqrtf(v + 1e-5f);
        float gamma = (tid < 64) ? g1[tid] : g2[tid - 64];
        float beta  = (tid < 64) ? h1[tid] : h2[tid - 64];
        float a = gamma * rstd;
        sa[tid] = a;
        sb[tid] = beta - m * a;
    }
    __syncthreads();
    int idx = blockIdx.x * blockDim.x + tid;
    if (idx >= NN * 32) return;
    int r = idx >> 5;
    int c4 = (idx & 31) << 2;
    float4 v = ((const float4*)g_raw1)[idx];
    float d = g_dinv[r];
    float o[4]; float vv[4] = {v.x, v.y, v.z, v.w};
    #pragma unroll
    for (int t = 0; t < 4; t++) {
        int c = c4 + t;
        float a = sa[c], b = sb[c];
        if (c4 < 64) o[t] = fmaxf(vv[t] * a + b, 0.f);
        else         o[t] = fmaxf(vv[t], 0.f) * a + b;
        o[t] *= d;
    }
    __half2 h0 = __floats2half2_rn(o[0], o[1]);
    __half2 h1v = __floats2half2_rn(o[2], o[3]);
    ((uint2*)g_y1h)[idx] = make_uint2(*(unsigned*)&h0, *(unsigned*)&h1v);
}

// ---------------- layer-2 GEMM: row-pair FFMA2 ----------------
__global__ void __launch_bounds__(256) k_gemm2(
        const float* __restrict__ A, const float* __restrict__ W1,
        const float* __restrict__ W2, const float* __restrict__ b1,
        const float* __restrict__ b2, float* __restrict__ C) {
    extern __shared__ float sm2[];
    float* Ws  = sm2;
    float* Ast = sm2 + 16384;
    int tid = threadIdx.x;
    int row0 = blockIdx.x * 64;

    for (int i = tid; i < 2048; i += 256) {
        int k = i >> 5, q = i & 31;
        ((float4*)(Ws + k * 256))[q]       = ((const float4*)(W1 + k * 128))[q];
        ((float4*)(Ws + k * 256 + 128))[q] = ((const float4*)(W2 + k * 128))[q];
    }
    for (int i = tid; i < 2048; i += 256) {
        int r = i >> 5, q = i & 31;
        float4 v = make_float4(0.f, 0.f, 0.f, 0.f);
        if (row0 + r < NN) v = ((const float4*)(A + (size_t)(row0 + r) * 128))[q];
        int k = q * 4;
        Ast[(k + 0) * 66 + r] = v.x;
        Ast[(k + 1) * 66 + r] = v.y;
        Ast[(k + 2) * 66 + r] = v.z;
        Ast[(k + 3) * 66 + r] = v.w;
    }
    __syncthreads();

    int tx = tid & 31, ty = tid >> 5;
    ull acc[4][8];
    #pragma unroll
    for (int i = 0; i < 4; i++)
        #pragma unroll
        for (int j = 0; j < 8; j++) acc[i][j] = 0ull;

    #pragma unroll 4
    for (int k = 0; k < 64; k++) {
        ull alo[4], ahi[4], w2[8];
        #pragma unroll
        for (int i = 0; i < 4; i++) {
            alo[i] = *(const ull*)(Ast + k * 66 + ty * 8 + 2 * i);
            ahi[i] = *(const ull*)(Ast + (64 + k) * 66 + ty * 8 + 2 * i);
        }
        #pragma unroll
        for (int j = 0; j < 8; j++) {
            float w = Ws[k * 256 + tx + 32 * j];
            w2[j] = pack2(w, w);
        }
        #pragma unroll
        for (int i = 0; i < 4; i++)
            #pragma unroll
            for (int j = 0; j < 8; j++)
                ffma2(acc[i][j], (j < 4 ? alo[i] : ahi[i]), w2[j]);
    }

    float bb[8];
    #pragma unroll
    for (int j = 0; j < 8; j++)
        bb[j] = (j < 4) ? b1[tx + 32 * j] : b2[tx + 32 * j - 128];

    float ls[8], l2[8];
    #pragma unroll
    for (int j = 0; j < 8; j++) { ls[j] = 0.f; l2[j] = 0.f; }
    #pragma unroll
    for (int i = 0; i < 4; i++) {
        int r = row0 + ty * 8 + 2 * i;
        #pragma unroll
        for (int h = 0; h < 2; h++) {
            if (r + h < NN) {
                #pragma unroll
                for (int j = 0; j < 8; j++) {
                    float v = (h == 0 ? lo2(acc[i][j]) : hi2(acc[i][j])) + bb[j];
                    C[(size_t)(r + h) * 256 + tx + 32 * j] = v;
                    float sv = (j < 4) ? v : fmaxf(v, 0.f);
                    ls[j] += sv; l2[j] += sv * sv;
                }
            }
        }
    }
    __syncthreads();
    float* red = Ast;
    red[tid] = 0.f; red[tid + 256] = 0.f;
    __syncthreads();
    #pragma unroll
    for (int j = 0; j < 8; j++) {
        atomicAdd(&red[tx + 32 * j], ls[j]);
        atomicAdd(&red[256 + tx + 32 * j], l2[j]);
    }
    __syncthreads();
    atomicAdd(&g_ssum[256 + tid], red[tid]);
    atomicAdd(&g_ssq[256 + tid], red[tid + 256]);
}

// ---------------- layer-3 GEMM with BN-on-load + folded statfin, fp16 output ----------------
// dyn smem: sbn 512 + Ws 128*64 + Ast 64*130
__global__ void __launch_bounds__(256) k_gemm3(
        const float* __restrict__ raw2, const float* __restrict__ Wm3,
        const float* __restrict__ Wl3, __half* __restrict__ y3,
        const float* __restrict__ g1, const float* __restrict__ h1,
        const float* __restrict__ g2, const float* __restrict__ h2) {
    extern __shared__ float sm3[];
    float* sa  = sm3;            // 256
    float* sb  = sm3 + 256;      // 256
    float* Ws  = sm3 + 512;      // [k][64], k<128
    float* Ast = sm3 + 512 + 8192; // [kk][r] stride 130, kk<64
    int tid = threadIdx.x;
    int row0 = blockIdx.x * 128;

    {   // folded statfin for layer-2 channels
        float m = g_ssum[256 + tid] * (1.0f / NN);
        float v = g_ssq[256 + tid] * (1.0f / NN) - m * m;
        float rstd = rsqrtf(v + 1e-5f);
        float gamma = (tid < 128) ? g1[tid] : g2[tid - 128];
        float beta  = (tid < 128) ? h1[tid] : h2[tid - 128];
        float a = gamma * rstd;
        sa[tid] = a;
        sb[tid] = beta - m * a;
    }

    for (int i = tid; i < 2048; i += 256) {
        int k = i >> 4, q = i & 15;
        float4 v = (q < 8) ? ((const float4*)(Wm3 + k * 32))[q]
                           : ((const float4*)(Wl3 + k * 32))[q - 8];
        ((float4*)(Ws + k * 64))[q] = v;
    }

    int tx = tid & 15, ty = tid >> 4;
    int half_c = (tx >= 8) ? 1 : 0;
    ull acc[4][4];
    #pragma unroll
    for (int i = 0; i < 4; i++)
        #pragma unroll
        for (int j = 0; j < 4; j++) acc[i][j] = 0ull;

    for (int kt = 0; kt < 128; kt += 32) {
        __syncthreads();
        for (int i = tid; i < 2048; i += 256) {
            int r = i >> 4, q = i & 15;
            int half = q >> 3, kk = (q & 7) << 2;
            float4 v = make_float4(0.f, 0.f, 0.f, 0.f);
            if (row0 + r < NN)
                v = ((const float4*)(raw2 + (size_t)(row0 + r) * 256 + half * 128 + kt))[q & 7];
            float o[4]; float vv[4] = {v.x, v.y, v.z, v.w};
            #pragma unroll
            for (int t = 0; t < 4; t++) {
                int col = half * 128 + kt + kk + t;
                float a = sa[col], b = sb[col];
                if (half == 0) o[t] = fmaxf(vv[t] * a + b, 0.f);
                else           o[t] = fmaxf(vv[t], 0.f) * a + b;
                Ast[(half * 32 + kk + t) * 130 + r] = o[t];
            }
        }
        __syncthreads();
        #pragma unroll 8
        for (int k = 0; k < 32; k++) {
            float4 w = ((float4*)(Ws + (kt + k) * 64))[tx];
            ull w2[4];
            w2[0] = pack2(w.x, w.x); w2[1] = pack2(w.y, w.y);
            w2[2] = pack2(w.z, w.z); w2[3] = pack2(w.w, w.w);
            ull a2[4];
            #pragma unroll
            for (int i = 0; i < 4; i++)
                a2[i] = *(const ull*)(Ast + (half_c * 32 + k) * 130 + ty * 8 + 2 * i);
            #pragma unroll
            for (int i = 0; i < 4; i++)
                #pragma unroll
                for (int j = 0; j < 4; j++)
                    ffma2(acc[i][j], a2[i], w2[j]);
        }
    }
    #pragma unroll
    for (int i = 0; i < 4; i++) {
        int r = row0 + ty * 8 + 2 * i;
        if (r < NN) {
            float d = g_dinv[r];
            __half2 h0 = __floats2half2_rn(lo2(acc[i][0]) * d, lo2(acc[i][1]) * d);
            __half2 h1v = __floats2half2_rn(lo2(acc[i][2]) * d, lo2(acc[i][3]) * d);
            ((uint2*)(y3 + (size_t)r * 64))[tx] = make_uint2(*(unsigned*)&h0, *(unsigned*)&h1v);
        }
        if (r + 1 < NN) {
            float d = g_dinv[r + 1];
            __half2 h0 = __floats2half2_rn(hi2(acc[i][0]) * d, hi2(acc[i][1]) * d);
            __half2 h1v = __floats2half2_rn(hi2(acc[i][2]) * d, hi2(acc[i][3]) * d);
            ((uint2*)(y3 + (size_t)(r + 1) * 64))[tx] = make_uint2(*(unsigned*)&h0, *(unsigned*)&h1v);
        }
    }
}

// ---------------- decoder ----------------
__global__ void k_dec(const int* __restrict__ src, const int* __restrict__ dst,
                      const float* __restrict__ mu, float* __restrict__ probs) {
    int t = blockIdx.x * blockDim.x + threadIdx.x;
    int e = t >> 3, sub = t & 7;
    int s = src[e], d = dst[e];
    float4 a = __ldg((const float4*)(mu + s * 32 + sub * 4));
    float4 b = __ldg((const float4*)(mu + d * 32 + sub * 4));
    float p = a.x * b.x + a.y * b.y + a.z * b.z + a.w * b.w;
    p += __shfl_down_sync(~0u, p, 4);
    p += __shfl_down_sync(~0u, p, 2);
    p += __shfl_down_sync(~0u, p, 1);
    if (sub == 0) probs[e] = 1.f / (1.f + expf(-p));
}

// ---------------- launch ----------------
extern "C" void kernel_launch(void* const* d_in, const int* in_sizes, int n_in,
                              void* d_out, int out_size) {
    const float* x   = (const float*)d_in[0];
    const int* ei    = (const int*)d_in[1];
    const int* src   = ei;
    const int* dst   = ei + EE;
    const float* Wm1 = (const float*)d_in[2];
    const float* bm1 = (const float*)d_in[3];
    const float* gm1 = (const float*)d_in[4];
    const float* hm1 = (const float*)d_in[5];
    const float* Wm2 = (const float*)d_in[6];
    const float* bm2 = (const float*)d_in[7];
    const float* gm2 = (const float*)d_in[8];
    const float* hm2 = (const float*)d_in[9];
    const float* Wm3 = (const float*)d_in[10];
    const float* bm3 = (const float*)d_in[11];
    const float* Wl1 = (const float*)d_in[12];
    const float* bl1 = (const float*)d_in[13];
    const float* gl1 = (const float*)d_in[14];
    const float* hl1 = (const float*)d_in[15];
    const float* Wl2 = (const float*)d_in[16];
    const float* bl2 = (const float*)d_in[17];
    const float* gl2 = (const float*)d_in[18];
    const float* hl2 = (const float*)d_in[19];
    const float* Wl3 = (const float*)d_in[20];
    const float* bl3 = (const float*)d_in[21];

    float* out = (float*)d_out;
    float* out_probs = out;
    float* out_mu = out + EE;
    float* out_ls = out + EE + NN * 32;

    float *ax, *raw1, *agg1, *raw2;
    __half *y0h, *y1h, *y3h;
    cudaGetSymbolAddress((void**)&y0h, g_y0h);
    cudaGetSymbolAddress((void**)&ax, g_ax);
    cudaGetSymbolAddress((void**)&raw1, g_raw1);
    cudaGetSymbolAddress((void**)&y1h, g_y1h);
    cudaGetSymbolAddress((void**)&agg1, g_agg1);
    cudaGetSymbolAddress((void**)&raw2, g_raw2);
    cudaGetSymbolAddress((void**)&y3h, g_y3h);

    const int SM1 = (64 * 128 + 64 * 66) * 4;
    const int SM2 = (64 * 256 + 128 * 66) * 4;
    const int SM3 = (512 + 128 * 64 + 64 * 130) * 4;
    cudaFuncSetAttribute(k_gemm1, cudaFuncAttributeMaxDynamicSharedMemorySize, SM1);
    cudaFuncSetAttribute(k_gemm2, cudaFuncAttributeMaxDynamicSharedMemorySize, SM2);
    cudaFuncSetAttribute(k_gemm3, cudaFuncAttributeMaxDynamicSharedMemorySize, SM3);

    // setup + degree + CSR
    k_zero<<<196, 256>>>();
    k_indeg<<<3125, 256>>>(dst);
    k_dinv_y0<<<3125, 256>>>(x);
    k_scan1<<<49, 1024>>>();
    k_scan3<<<49, 1024>>>();
    k_scatter<<<3125, 256>>>(src, dst);

    // layer 1
    k_agg1h<<<6250, 256>>>(y0h, ax);
    k_gemm1<<<782, 256, SM1>>>(ax, Wm1, Wl1, bm1, bl1, raw1);
    k_ew1<<<6250, 256>>>(gm1, hm1, gl1, hl1);

    // layer 2
    k_agg2h<<<6250, 256>>>(y1h, agg1);
    k_gemm2<<<782, 256, SM2>>>(agg1, Wm2, Wl2, bm2, bl2, raw2);

    // layer 3 (statfin2 folded into gemm3)
    k_gemm3<<<391, 256, SM3>>>(raw2, Wm3, Wl3, y3h, gm2, hm2, gl2, hl2);
    k_agg3f<<<6250, 256>>>(y3h, out_mu, bm3, bl3, out_ls);

    // decoder
    k_dec<<<25000, 256>>>(src, dst, out_mu, out_probs);
}